// round 9
// baseline (speedup 1.0000x reference)
#include <cuda_runtime.h>
#include <cstdint>

#define BB 4
#define SS 2048
#define DDIM 1024
#define HH 16
#define DKK 64
#define MTOT (BB*SS)   // 8192

// ---------------- scratch (static __device__, allocation-free) ----------------
__device__ float g_Q[(size_t)MTOT*DDIM];
__device__ float g_K[(size_t)MTOT*DDIM];
__device__ float g_V[(size_t)MTOT*DDIM];
__device__ float g_A[(size_t)MTOT*DDIM];

// ---------------- helpers ----------------
__device__ __forceinline__ uint32_t f2tf32(float f) {
    uint32_t u;
    asm("cvt.rna.tf32.f32 %0, %1;" : "=r"(u) : "f"(f));
    return u;
}
__device__ __forceinline__ uint32_t bits2tf32(uint32_t b) {
    return f2tf32(__uint_as_float(b));
}
__device__ __forceinline__ float ex2(float x) {
    float y;
    asm("ex2.approx.ftz.f32 %0, %1;" : "=f"(y) : "f"(x));
    return y;
}
__device__ __forceinline__ void cp16(uint32_t saddr, const void* g) {
    asm volatile("cp.async.cg.shared.global [%0], [%1], 16;" :: "r"(saddr), "l"(g));
}
__device__ __forceinline__ void cp4(uint32_t saddr, const void* g) {
    asm volatile("cp.async.ca.shared.global [%0], [%1], 4;" :: "r"(saddr), "l"(g));
}
__device__ __forceinline__ void cp_commit() {
    asm volatile("cp.async.commit_group;");
}
template <int N>
__device__ __forceinline__ void cp_wait() {
    asm volatile("cp.async.wait_group %0;" :: "n"(N));
}
// 8x8 tf32 tile == one b16 ldmatrix unit (8 rows x 16B); thread t gets (row t/4, col t%4)
__device__ __forceinline__ void ldsm4(uint32_t& r0, uint32_t& r1, uint32_t& r2, uint32_t& r3,
                                      uint32_t addr) {
    asm volatile("ldmatrix.sync.aligned.m8n8.x4.shared.b16 {%0,%1,%2,%3}, [%4];"
                 : "=r"(r0), "=r"(r1), "=r"(r2), "=r"(r3) : "r"(addr));
}

// D(16x8,f32) += A(16x8,tf32,row) * B(8x8,tf32,col)
__device__ __forceinline__ void mma_tf32(float c[4],
                                         uint32_t a0, uint32_t a1, uint32_t a2, uint32_t a3,
                                         uint32_t b0, uint32_t b1) {
    asm volatile(
        "mma.sync.aligned.m16n8k8.row.col.f32.tf32.tf32.f32 "
        "{%0,%1,%2,%3}, {%4,%5,%6,%7}, {%8,%9}, {%0,%1,%2,%3};"
        : "+f"(c[0]), "+f"(c[1]), "+f"(c[2]), "+f"(c[3])
        : "r"(a0), "r"(a1), "r"(a2), "r"(a3), "r"(b0), "r"(b1));
}

// ---------------- GEMM: C[m][n] = sum_k A[m][k] * W[n][k] (R7 proven config) ----------------
#define GBM 128
#define GBN 128
#define GBK 32
#define GST (GBK + 4)
#define GSTG (GBM * GST)
#define GNS 3
#define GSMEM (2 * GNS * GSTG * 4)            // 110592 B

__global__ __launch_bounds__(256, 2)
void gemm_nt(const float* __restrict__ A0, const float* __restrict__ A1, const float* __restrict__ A2,
             const float* __restrict__ W0, const float* __restrict__ W1, const float* __restrict__ W2,
             float* __restrict__ C0, float* __restrict__ C1, float* __restrict__ C2,
             int roundOut) {
    extern __shared__ float gsm[];
    float* Asm = gsm;
    float* Bsm = gsm + GNS * GSTG;

    const int z = blockIdx.z;
    const float* A = (z == 0) ? A0 : (z == 1) ? A1 : A2;
    const float* W = (z == 0) ? W0 : (z == 1) ? W1 : W2;
    float*       C = (z == 0) ? C0 : (z == 1) ? C1 : C2;

    const int m0 = blockIdx.y * GBM;
    const int n0 = blockIdx.x * GBN;
    const int tid = threadIdx.x;
    const int w = tid >> 5, lane = tid & 31;
    const int g = lane >> 2, tig = lane & 3;
    const int wm = (w >> 2) * 64;
    const int wn = (w & 3) * 32;

    const int lr = tid >> 3;
    const int lc = (tid & 7) << 2;

    const uint32_t sA = (uint32_t)__cvta_generic_to_shared(Asm);
    const uint32_t sB = (uint32_t)__cvta_generic_to_shared(Bsm);

    const int lane7 = lane & 7;
    const int a_ro = ((lane >> 3) & 1) * 8;
    const int a_ko = ((lane >> 4) & 1) * 4;
    const int b_no = ((lane >> 4) & 1) * 8;
    const int b_ko = ((lane >> 3) & 1) * 4;

    uint32_t aIdx[4];
#pragma unroll
    for (int mt = 0; mt < 4; mt++)
        aIdx[mt] = (uint32_t)(((wm + mt * 16 + a_ro + lane7) * GST + a_ko) * 4);
    const uint32_t bIdx = (uint32_t)(((wn + b_no + lane7) * GST + b_ko) * 4);

    float acc[4][4][4];
#pragma unroll
    for (int i = 0; i < 4; i++)
#pragma unroll
        for (int j = 0; j < 4; j++)
#pragma unroll
            for (int e = 0; e < 4; e++) acc[i][j][e] = 0.f;

    auto issue = [&](int st, int k0) {
#pragma unroll
        for (int it = 0; it < 4; it++) {
            int row = lr + it * 32;
            cp16(sA + (uint32_t)((st * GBM + row) * GST + lc) * 4,
                 &A[(size_t)(m0 + row) * DDIM + k0 + lc]);
            cp16(sB + (uint32_t)((st * GBN + row) * GST + lc) * 4,
                 &W[(size_t)(n0 + row) * DDIM + k0 + lc]);
        }
    };

    issue(0, 0); cp_commit();
    issue(1, GBK); cp_commit();

    const int NKT = DDIM / GBK;
    for (int kt = 0; kt < NKT; kt++) {
        if (kt < NKT - 1) cp_wait<1>(); else cp_wait<0>();
        __syncthreads();

        const int st = kt % GNS;
        const uint32_t stb = (uint32_t)(st * GSTG * 4);

#pragma unroll
        for (int ks = 0; ks < 4; ks++) {
            const uint32_t ksB = (uint32_t)(ks * 32);
            uint32_t b[4][2];
            uint32_t bb = sB + stb + bIdx + ksB;
            ldsm4(b[0][0], b[0][1], b[1][0], b[1][1], bb);
            ldsm4(b[2][0], b[2][1], b[3][0], b[3][1], bb + 16 * GST * 4);
            uint32_t a[4][4];
#pragma unroll
            for (int mt = 0; mt < 4; mt++)
                ldsm4(a[mt][0], a[mt][1], a[mt][2], a[mt][3], sA + stb + aIdx[mt] + ksB);

#pragma unroll
            for (int nt = 0; nt < 4; nt++) {
                b[nt][0] = bits2tf32(b[nt][0]);
                b[nt][1] = bits2tf32(b[nt][1]);
            }
#pragma unroll
            for (int mt = 0; mt < 4; mt++) {
#pragma unroll
                for (int e = 0; e < 4; e++) a[mt][e] = bits2tf32(a[mt][e]);
#pragma unroll
                for (int nt = 0; nt < 4; nt++)
                    mma_tf32(acc[mt][nt], a[mt][0], a[mt][1], a[mt][2], a[mt][3],
                             b[nt][0], b[nt][1]);
            }
        }

        if (kt + 2 < NKT) {
            issue((kt + 2) % GNS, (kt + 2) * GBK);
            cp_commit();
        }
    }

#pragma unroll
    for (int mt = 0; mt < 4; mt++) {
        int r0 = m0 + wm + mt * 16 + g;
#pragma unroll
        for (int nt = 0; nt < 4; nt++) {
            int col = n0 + wn + nt * 8 + 2 * tig;
            float v0 = acc[mt][nt][0], v1 = acc[mt][nt][1];
            float v2 = acc[mt][nt][2], v3 = acc[mt][nt][3];
            if (roundOut) {
                v0 = __uint_as_float(f2tf32(v0)); v1 = __uint_as_float(f2tf32(v1));
                v2 = __uint_as_float(f2tf32(v2)); v3 = __uint_as_float(f2tf32(v3));
            }
            *reinterpret_cast<float2*>(&C[(size_t)r0 * DDIM + col]) = make_float2(v0, v1);
            *reinterpret_cast<float2*>(&C[(size_t)(r0 + 8) * DDIM + col]) = make_float2(v2, v3);
        }
    }
}

// ---------------- flash attention: 256-row Q tile, 3-stage K/V, single sync/tile ----------------
#define AQT 256
#define ATHR 256
#define AP 68    // K/P stride: LDSM conflict-free
#define VP 72    // V stride: scalar B-frag loads conflict-free
#define ANS 3
#define ASMEM ((ANS*64*AP + ANS*64*VP + AQT*AP) * 4 + ANS * 64 * 4)   // 177920 B

__global__ __launch_bounds__(ATHR, 1)
void attn_kernel(const float* __restrict__ Q, const float* __restrict__ K,
                 const float* __restrict__ V, const int* __restrict__ mask,
                 float* __restrict__ O) {
    extern __shared__ uint32_t smem_u[];
    uint32_t* Ks0 = smem_u;                      // ANS stages x 64 rows (stride AP)
    uint32_t* Vs0 = Ks0 + ANS * 64 * AP;         // ANS stages x 64 rows (stride VP)
    uint32_t* Ps  = Vs0 + ANS * 64 * VP;         // AQT rows (Q staging + P)
    int* msk0 = (int*)(Ps + AQT * AP);           // ANS stages x 64

    const int qi = gridDim.x - 1 - blockIdx.x;   // heavy tiles first
    const int bh = blockIdx.y;
    const int b = bh / HH, h = bh % HH;

    const int tid = threadIdx.x;
    const int w = tid >> 5, lane = tid & 31;
    const int g = lane >> 2, tig = lane & 3;
    const int wrow = w * 32;

    const float* Qb = Q + ((size_t)b * SS + (size_t)qi * AQT) * DDIM + h * DKK;
    const float* Kb = K + (size_t)b * SS * DDIM + h * DKK;
    const float* Vb = V + (size_t)b * SS * DDIM + h * DKK;
    float* Ob = O + ((size_t)b * SS + (size_t)qi * AQT) * DDIM + h * DKK;

    const uint32_t sK = (uint32_t)__cvta_generic_to_shared(Ks0);
    const uint32_t sV = (uint32_t)__cvta_generic_to_shared(Vs0);
    const uint32_t sP = (uint32_t)__cvta_generic_to_shared(Ps);
    const uint32_t sM = (uint32_t)__cvta_generic_to_shared(msk0);

    const int lane7 = lane & 7;
    const int a_ro = ((lane >> 3) & 1) * 8;
    const int a_ko = ((lane >> 4) & 1) * 4;
    const int b_no = ((lane >> 4) & 1) * 8;
    const int b_ko = ((lane >> 3) & 1) * 4;

    const float qscale = 0.125f * 1.4426950408889634f;

    auto issueKV = [&](int st, int kt) {
        const float* Kt = Kb + (size_t)kt * 64 * DDIM;
        const float* Vt = Vb + (size_t)kt * 64 * DDIM;
#pragma unroll
        for (int t = 0; t < 4; t++) {
            int i = tid + t * ATHR;
            int r = i >> 4;
            int c4 = (i & 15) << 2;
            cp16(sK + (uint32_t)((st * 64 + r) * AP + c4) * 4, Kt + (size_t)r * DDIM + c4);
            cp16(sV + (uint32_t)((st * 64 + r) * VP + c4) * 4, Vt + (size_t)r * DDIM + c4);
        }
        if (tid < 64) cp4(sM + (uint32_t)(st * 64 + tid) * 4, &mask[(size_t)b * SS + kt * 64 + tid]);
    };

    const int ktmax = 4 * qi + 3;   // >= 3
    issueKV(0, 0); cp_commit();
    issueKV(1, 1); cp_commit();

    // stage Q (AQT x 64), scale+round, then pull fragments via ldmatrix
#pragma unroll
    for (int t = 0; t < 16; t++) {
        int i = tid + t * ATHR;
        int r = i >> 4;
        int c4 = (i & 15) << 2;
        float4 v = *reinterpret_cast<const float4*>(Qb + (size_t)r * DDIM + c4);
        uint4 u = make_uint4(f2tf32(v.x * qscale), f2tf32(v.y * qscale),
                             f2tf32(v.z * qscale), f2tf32(v.w * qscale));
        *reinterpret_cast<uint4*>(&Ps[r * AP + c4]) = u;
    }
    __syncthreads();

    uint32_t qf[2][8][4];
#pragma unroll
    for (int mt = 0; mt < 2; mt++) {
        const uint32_t base = sP + (uint32_t)(((wrow + mt * 16 + a_ro + lane7) * AP + a_ko) * 4);
#pragma unroll
        for (int ks = 0; ks < 8; ks++)
            ldsm4(qf[mt][ks][0], qf[mt][ks][1], qf[mt][ks][2], qf[mt][ks][3],
                  base + (uint32_t)(ks * 32));
    }

    float mrow[2][2], lrow[2][2];
    float o[2][8][4];
#pragma unroll
    for (int mt = 0; mt < 2; mt++) {
        mrow[mt][0] = mrow[mt][1] = -1e30f;
        lrow[mt][0] = lrow[mt][1] = 0.f;
#pragma unroll
        for (int nt = 0; nt < 8; nt++)
#pragma unroll
            for (int e = 0; e < 4; e++) o[mt][nt][e] = 0.f;
    }

    const int rowmax = qi * AQT + wrow + 31;

    for (int kt = 0; kt <= ktmax; kt++) {
        const int st = kt % ANS;
        if (kt < ktmax) cp_wait<1>(); else cp_wait<0>();
        __syncthreads();

        // prefetch stage kt+2 (its previous consumer was tile kt-1; everyone
        // passed this tile's barrier after finishing kt-1)
        if (kt + 2 <= ktmax) {
            issueKV((kt + 2) % ANS, kt + 2);
            cp_commit();
        }

        if (kt * 64 > rowmax) continue;   // warp-uniform skip of fully-masked tiles

        const uint32_t sKst = sK + (uint32_t)(st * 64 * AP * 4);
        const uint32_t* Vsr = Vs0 + st * 64 * VP;
        const int* msk = msk0 + st * 64;

        const int mvl0 = msk[lane], mvl1 = msk[32 + lane];
        const bool allvalid = __all_sync(0xffffffffu, (mvl0 != 0) && (mvl1 != 0));

        // S = Q @ K^T : 32x64 per warp
        float s[2][8][4];
#pragma unroll
        for (int mt = 0; mt < 2; mt++)
#pragma unroll
            for (int nt = 0; nt < 8; nt++)
                s[mt][nt][0] = s[mt][nt][1] = s[mt][nt][2] = s[mt][nt][3] = 0.f;

        const uint32_t kb0 = sKst + (uint32_t)(((b_no + lane7) * AP + b_ko) * 4);
#pragma unroll
        for (int ks = 0; ks < 8; ks++) {
            const uint32_t ksB = (uint32_t)(ks * 32);
            uint32_t bf[8][2];
#pragma unroll
            for (int j = 0; j < 4; j++)
                ldsm4(bf[2*j][0], bf[2*j][1], bf[2*j+1][0], bf[2*j+1][1],
                      kb0 + (uint32_t)(j * 16 * AP * 4) + ksB);
#pragma unroll
            for (int mt = 0; mt < 2; mt++)
#pragma unroll
                for (int nt = 0; nt < 8; nt++)
                    mma_tf32(s[mt][nt], qf[mt][ks][0], qf[mt][ks][1],
                             qf[mt][ks][2], qf[mt][ks][3], bf[nt][0], bf[nt][1]);
        }

        // masking + online softmax (rescale-skip vote)
#pragma unroll
        for (int mt = 0; mt < 2; mt++) {
            const int q0 = qi * AQT + wrow + mt * 16 + g;
            const int q1 = q0 + 8;
            const bool needc = (kt * 64 + 63 > qi * AQT + wrow + mt * 16);

            if (!allvalid) {
#pragma unroll
                for (int nt = 0; nt < 8; nt++) {
                    int cl = nt * 8 + 2 * tig;
                    int cg = kt * 64 + cl;
                    bool mv0 = (msk[cl] != 0);
                    bool mv1 = (msk[cl + 1] != 0);
                    if (!mv0 || (needc && cg > q0))     s[mt][nt][0] = -1e30f;
                    if (!mv1 || (needc && cg + 1 > q0)) s[mt][nt][1] = -1e30f;
                    if (!mv0 || (needc && cg > q1))     s[mt][nt][2] = -1e30f;
                    if (!mv1 || (needc && cg + 1 > q1)) s[mt][nt][3] = -1e30f;
                }
            } else if (needc) {
#pragma unroll
                for (int nt = 0; nt < 8; nt++) {
                    int cg = kt * 64 + nt * 8 + 2 * tig;
                    if (cg > q0)     s[mt][nt][0] = -1e30f;
                    if (cg + 1 > q0) s[mt][nt][1] = -1e30f;
                    if (cg > q1)     s[mt][nt][2] = -1e30f;
                    if (cg + 1 > q1) s[mt][nt][3] = -1e30f;
                }
            }

            float rm0 = -1e30f, rm1 = -1e30f;
#pragma unroll
            for (int nt = 0; nt < 8; nt++) {
                rm0 = fmaxf(rm0, fmaxf(s[mt][nt][0], s[mt][nt][1]));
                rm1 = fmaxf(rm1, fmaxf(s[mt][nt][2], s[mt][nt][3]));
            }
            rm0 = fmaxf(rm0, __shfl_xor_sync(0xffffffffu, rm0, 1));
            rm0 = fmaxf(rm0, __shfl_xor_sync(0xffffffffu, rm0, 2));
            rm1 = fmaxf(rm1, __shfl_xor_sync(0xffffffffu, rm1, 1));
            rm1 = fmaxf(rm1, __shfl_xor_sync(0xffffffffu, rm1, 2));

            const float oldm0 = mrow[mt][0], oldm1 = mrow[mt][1];
            float mn0 = fmaxf(oldm0, rm0);
            float mn1 = fmaxf(oldm1, rm1);
            mrow[mt][0] = mn0; mrow[mt][1] = mn1;

            const bool nochg = (mn0 == oldm0) && (mn1 == oldm1);
            const bool skipresc = __all_sync(0xffffffffu, nochg);
            float al0 = 1.f, al1 = 1.f;
            if (!skipresc) {
                al0 = ex2(oldm0 - mn0);
                al1 = ex2(oldm1 - mn1);
            }

            float rs0 = 0.f, rs1 = 0.f;
            const int pr = wrow + mt * 16;
#pragma unroll
            for (int nt = 0; nt < 8; nt++) {
                int cl = nt * 8 + 2 * tig;
                float p0 = ex2(s[mt][nt][0] - mn0);
                float p1 = ex2(s[mt][nt][1] - mn0);
                float p2 = ex2(s[mt][nt][2] - mn1);
                float p3 = ex2(s[mt][nt][3] - mn1);
                rs0 += p0 + p1;
                rs1 += p2 + p3;
                *reinterpret_cast<uint2*>(&Ps[(pr + g) * AP + cl]) =
                    make_uint2(f2tf32(p0), f2tf32(p1));
                *reinterpret_cast<uint2*>(&Ps[(pr + g + 8) * AP + cl]) =
                    make_uint2(f2tf32(p2), f2tf32(p3));
            }
            rs0 += __shfl_xor_sync(0xffffffffu, rs0, 1);
            rs0 += __shfl_xor_sync(0xffffffffu, rs0, 2);
            rs1 += __shfl_xor_sync(0xffffffffu, rs1, 1);
            rs1 += __shfl_xor_sync(0xffffffffu, rs1, 2);
            lrow[mt][0] = lrow[mt][0] * al0 + rs0;
            lrow[mt][1] = lrow[mt][1] * al1 + rs1;

            if (!skipresc) {
#pragma unroll
                for (int nt = 0; nt < 8; nt++) {
                    o[mt][nt][0] *= al0; o[mt][nt][1] *= al0;
                    o[mt][nt][2] *= al1; o[mt][nt][3] *= al1;
                }
            }
        }
        __syncwarp();

        // O += P @ V : P frags via ldmatrix, V scalar (conflict-free at stride 72)
#pragma unroll
        for (int ks = 0; ks < 8; ks++) {
            int kk = ks * 8;
            uint32_t vb[8][2];
#pragma unroll
            for (int nt = 0; nt < 8; nt++) {
                vb[nt][0] = Vsr[(kk + tig) * VP + nt * 8 + g];
                vb[nt][1] = Vsr[(kk + tig + 4) * VP + nt * 8 + g];
            }
#pragma unroll
            for (int mt = 0; mt < 2; mt++) {
                const int pr = wrow + mt * 16;
                uint32_t a0, a1, a2, a3;
                ldsm4(a0, a1, a2, a3,
                      sP + (uint32_t)(((pr + a_ro + lane7) * AP + kk + a_ko) * 4));
#pragma unroll
                for (int nt = 0; nt < 8; nt++)
                    mma_tf32(o[mt][nt], a0, a1, a2, a3, vb[nt][0], vb[nt][1]);
            }
        }
    }

    // normalize + store (rounded: feeds the Wo tf32 GEMM)
#pragma unroll
    for (int mt = 0; mt < 2; mt++) {
        float i0 = 1.f / lrow[mt][0];
        float i1 = 1.f / lrow[mt][1];
        int r0 = wrow + mt * 16 + g;
#pragma unroll
        for (int nt = 0; nt < 8; nt++) {
            int cl = nt * 8 + 2 * tig;
            *reinterpret_cast<float2*>(&Ob[(size_t)r0 * DDIM + cl]) =
                make_float2(__uint_as_float(f2tf32(o[mt][nt][0] * i0)),
                            __uint_as_float(f2tf32(o[mt][nt][1] * i0)));
            *reinterpret_cast<float2*>(&Ob[(size_t)(r0 + 8) * DDIM + cl]) =
                make_float2(__uint_as_float(f2tf32(o[mt][nt][2] * i1)),
                            __uint_as_float(f2tf32(o[mt][nt][3] * i1)));
        }
    }
}

// ---------------- launch ----------------
extern "C" void kernel_launch(void* const* d_in, const int* in_sizes, int n_in,
                              void* d_out, int out_size) {
    const float* xq = (const float*)d_in[0];
    const float* xk = (const float*)d_in[1];
    const float* xv = (const float*)d_in[2];
    const int* mask = (const int*)d_in[3];
    const float* Wq = (const float*)d_in[4];
    const float* Wk = (const float*)d_in[5];
    const float* Wv = (const float*)d_in[6];
    const float* Wo = (const float*)d_in[7];
    float* out = (float*)d_out;

    float *Qp, *Kp, *Vp, *Ap;
    cudaGetSymbolAddress((void**)&Qp, g_Q);
    cudaGetSymbolAddress((void**)&Kp, g_K);
    cudaGetSymbolAddress((void**)&Vp, g_V);
    cudaGetSymbolAddress((void**)&Ap, g_A);

    cudaFuncSetAttribute(gemm_nt, cudaFuncAttributeMaxDynamicSharedMemorySize, GSMEM);
    cudaFuncSetAttribute(attn_kernel, cudaFuncAttributeMaxDynamicSharedMemorySize, ASMEM);

    // fused QKV projections; outputs rounded to tf32 for attention consumption
    gemm_nt<<<dim3(DDIM / GBN, MTOT / GBM, 3), 256, GSMEM>>>(
        xq, xk, xv, Wq, Wk, Wv, Qp, Kp, Vp, 1);

    attn_kernel<<<dim3(SS / AQT, BB * HH), ATHR, ASMEM>>>(Qp, Kp, Vp, mask, Ap);

    // output projection; exact fp32 output
    gemm_nt<<<dim3(DDIM / GBN, MTOT / GBM, 1), 256, GSMEM>>>(
        Ap, Ap, Ap, Wo, Wo, Wo, out, out, out, 0);
}

// round 10
// speedup vs baseline: 1.0202x; 1.0202x over previous
#include <cuda_runtime.h>
#include <cuda_fp16.h>
#include <cstdint>

#define BB 4
#define SS 2048
#define DDIM 1024
#define HH 16
#define DKK 64
#define MTOT (BB*SS)   // 8192

// ---------------- scratch (static __device__, allocation-free) ----------------
__device__ float g_Q[(size_t)MTOT*DDIM];
__device__ float g_K[(size_t)MTOT*DDIM];
__device__ float g_A[(size_t)MTOT*DDIM];
__device__ __half g_Vh[(size_t)MTOT*DDIM];
__device__ __half g_Vl[(size_t)MTOT*DDIM];

// ---------------- helpers ----------------
__device__ __forceinline__ uint32_t f2tf32(float f) {
    uint32_t u;
    asm("cvt.rna.tf32.f32 %0, %1;" : "=r"(u) : "f"(f));
    return u;
}
__device__ __forceinline__ uint32_t bits2tf32(uint32_t b) {
    return f2tf32(__uint_as_float(b));
}
__device__ __forceinline__ float ex2(float x) {
    float y;
    asm("ex2.approx.ftz.f32 %0, %1;" : "=f"(y) : "f"(x));
    return y;
}
__device__ __forceinline__ uint32_t packh2(float lo, float hi) {
    __half2 h = __floats2half2_rn(lo, hi);   // x (low) = lo, y (high) = hi
    return *reinterpret_cast<uint32_t*>(&h);
}
__device__ __forceinline__ void cp16(uint32_t saddr, const void* g) {
    asm volatile("cp.async.cg.shared.global [%0], [%1], 16;" :: "r"(saddr), "l"(g));
}
__device__ __forceinline__ void cp4(uint32_t saddr, const void* g) {
    asm volatile("cp.async.ca.shared.global [%0], [%1], 4;" :: "r"(saddr), "l"(g));
}
__device__ __forceinline__ void cp_commit() {
    asm volatile("cp.async.commit_group;");
}
template <int N>
__device__ __forceinline__ void cp_wait() {
    asm volatile("cp.async.wait_group %0;" :: "n"(N));
}
__device__ __forceinline__ void ldsm4(uint32_t& r0, uint32_t& r1, uint32_t& r2, uint32_t& r3,
                                      uint32_t addr) {
    asm volatile("ldmatrix.sync.aligned.m8n8.x4.shared.b16 {%0,%1,%2,%3}, [%4];"
                 : "=r"(r0), "=r"(r1), "=r"(r2), "=r"(r3) : "r"(addr));
}
__device__ __forceinline__ void ldsm4t(uint32_t& r0, uint32_t& r1, uint32_t& r2, uint32_t& r3,
                                       uint32_t addr) {
    asm volatile("ldmatrix.sync.aligned.m8n8.x4.trans.shared.b16 {%0,%1,%2,%3}, [%4];"
                 : "=r"(r0), "=r"(r1), "=r"(r2), "=r"(r3) : "r"(addr));
}

// D(16x8,f32) += A(16x8,tf32,row) * B(8x8,tf32,col)
__device__ __forceinline__ void mma_tf32(float c[4],
                                         uint32_t a0, uint32_t a1, uint32_t a2, uint32_t a3,
                                         uint32_t b0, uint32_t b1) {
    asm volatile(
        "mma.sync.aligned.m16n8k8.row.col.f32.tf32.tf32.f32 "
        "{%0,%1,%2,%3}, {%4,%5,%6,%7}, {%8,%9}, {%0,%1,%2,%3};"
        : "+f"(c[0]), "+f"(c[1]), "+f"(c[2]), "+f"(c[3])
        : "r"(a0), "r"(a1), "r"(a2), "r"(a3), "r"(b0), "r"(b1));
}
// D(16x8,f32) += A(16x16,f16,row) * B(16x8,f16,col)
__device__ __forceinline__ void mma_f16(float c[4],
                                        uint32_t a0, uint32_t a1, uint32_t a2, uint32_t a3,
                                        uint32_t b0, uint32_t b1) {
    asm volatile(
        "mma.sync.aligned.m16n8k16.row.col.f32.f16.f16.f32 "
        "{%0,%1,%2,%3}, {%4,%5,%6,%7}, {%8,%9}, {%0,%1,%2,%3};"
        : "+f"(c[0]), "+f"(c[1]), "+f"(c[2]), "+f"(c[3])
        : "r"(a0), "r"(a1), "r"(a2), "r"(a3), "r"(b0), "r"(b1));
}

// ---------------- GEMM: C[m][n] = sum_k A[m][k] * W[n][k] (R7 proven config) ----------------
#define GBM 128
#define GBN 128
#define GBK 32
#define GST (GBK + 4)
#define GSTG (GBM * GST)
#define GNS 3
#define GSMEM (2 * GNS * GSTG * 4)            // 110592 B

__global__ __launch_bounds__(256, 2)
void gemm_nt(const float* __restrict__ A0, const float* __restrict__ A1, const float* __restrict__ A2,
             const float* __restrict__ W0, const float* __restrict__ W1, const float* __restrict__ W2,
             float* __restrict__ C0, float* __restrict__ C1, float* __restrict__ C2,
             __half* __restrict__ VH, __half* __restrict__ VL,
             int roundOut, int vhalf) {
    extern __shared__ float gsm[];
    float* Asm = gsm;
    float* Bsm = gsm + GNS * GSTG;

    const int z = blockIdx.z;
    const float* A = (z == 0) ? A0 : (z == 1) ? A1 : A2;
    const float* W = (z == 0) ? W0 : (z == 1) ? W1 : W2;
    float*       C = (z == 0) ? C0 : (z == 1) ? C1 : C2;

    const int m0 = blockIdx.y * GBM;
    const int n0 = blockIdx.x * GBN;
    const int tid = threadIdx.x;
    const int w = tid >> 5, lane = tid & 31;
    const int g = lane >> 2, tig = lane & 3;
    const int wm = (w >> 2) * 64;
    const int wn = (w & 3) * 32;

    const int lr = tid >> 3;
    const int lc = (tid & 7) << 2;

    const uint32_t sA = (uint32_t)__cvta_generic_to_shared(Asm);
    const uint32_t sB = (uint32_t)__cvta_generic_to_shared(Bsm);

    const int lane7 = lane & 7;
    const int a_ro = ((lane >> 3) & 1) * 8;
    const int a_ko = ((lane >> 4) & 1) * 4;
    const int b_no = ((lane >> 4) & 1) * 8;
    const int b_ko = ((lane >> 3) & 1) * 4;

    uint32_t aIdx[4];
#pragma unroll
    for (int mt = 0; mt < 4; mt++)
        aIdx[mt] = (uint32_t)(((wm + mt * 16 + a_ro + lane7) * GST + a_ko) * 4);
    const uint32_t bIdx = (uint32_t)(((wn + b_no + lane7) * GST + b_ko) * 4);

    float acc[4][4][4];
#pragma unroll
    for (int i = 0; i < 4; i++)
#pragma unroll
        for (int j = 0; j < 4; j++)
#pragma unroll
            for (int e = 0; e < 4; e++) acc[i][j][e] = 0.f;

    auto issue = [&](int st, int k0) {
#pragma unroll
        for (int it = 0; it < 4; it++) {
            int row = lr + it * 32;
            cp16(sA + (uint32_t)((st * GBM + row) * GST + lc) * 4,
                 &A[(size_t)(m0 + row) * DDIM + k0 + lc]);
            cp16(sB + (uint32_t)((st * GBN + row) * GST + lc) * 4,
                 &W[(size_t)(n0 + row) * DDIM + k0 + lc]);
        }
    };

    issue(0, 0); cp_commit();
    issue(1, GBK); cp_commit();

    const int NKT = DDIM / GBK;
    for (int kt = 0; kt < NKT; kt++) {
        if (kt < NKT - 1) cp_wait<1>(); else cp_wait<0>();
        __syncthreads();

        const int st = kt % GNS;
        const uint32_t stb = (uint32_t)(st * GSTG * 4);

#pragma unroll
        for (int ks = 0; ks < 4; ks++) {
            const uint32_t ksB = (uint32_t)(ks * 32);
            uint32_t b[4][2];
            uint32_t bb = sB + stb + bIdx + ksB;
            ldsm4(b[0][0], b[0][1], b[1][0], b[1][1], bb);
            ldsm4(b[2][0], b[2][1], b[3][0], b[3][1], bb + 16 * GST * 4);
            uint32_t a[4][4];
#pragma unroll
            for (int mt = 0; mt < 4; mt++)
                ldsm4(a[mt][0], a[mt][1], a[mt][2], a[mt][3], sA + stb + aIdx[mt] + ksB);

#pragma unroll
            for (int nt = 0; nt < 4; nt++) {
                b[nt][0] = bits2tf32(b[nt][0]);
                b[nt][1] = bits2tf32(b[nt][1]);
            }
#pragma unroll
            for (int mt = 0; mt < 4; mt++) {
#pragma unroll
                for (int e = 0; e < 4; e++) a[mt][e] = bits2tf32(a[mt][e]);
#pragma unroll
                for (int nt = 0; nt < 4; nt++)
                    mma_tf32(acc[mt][nt], a[mt][0], a[mt][1], a[mt][2], a[mt][3],
                             b[nt][0], b[nt][1]);
            }
        }

        if (kt + 2 < NKT) {
            issue((kt + 2) % GNS, (kt + 2) * GBK);
            cp_commit();
        }
    }

    const bool toHalf = (vhalf != 0) && (z == 2);
#pragma unroll
    for (int mt = 0; mt < 4; mt++) {
        int r0 = m0 + wm + mt * 16 + g;
#pragma unroll
        for (int nt = 0; nt < 4; nt++) {
            int col = n0 + wn + nt * 8 + 2 * tig;
            float v0 = acc[mt][nt][0], v1 = acc[mt][nt][1];
            float v2 = acc[mt][nt][2], v3 = acc[mt][nt][3];
            if (toHalf) {
                // V: split into fp16 hi + fp16 lo (residual) for compensated PV
                __half h0 = __float2half_rn(v0), h1 = __float2half_rn(v1);
                __half h2 = __float2half_rn(v2), h3 = __float2half_rn(v3);
                __half l0 = __float2half_rn(v0 - __half2float(h0));
                __half l1 = __float2half_rn(v1 - __half2float(h1));
                __half l2 = __float2half_rn(v2 - __half2float(h2));
                __half l3 = __float2half_rn(v3 - __half2float(h3));
                *reinterpret_cast<__half2*>(&VH[(size_t)r0 * DDIM + col]) = __halves2half2(h0, h1);
                *reinterpret_cast<__half2*>(&VH[(size_t)(r0 + 8) * DDIM + col]) = __halves2half2(h2, h3);
                *reinterpret_cast<__half2*>(&VL[(size_t)r0 * DDIM + col]) = __halves2half2(l0, l1);
                *reinterpret_cast<__half2*>(&VL[(size_t)(r0 + 8) * DDIM + col]) = __halves2half2(l2, l3);
            } else {
                if (roundOut) {
                    v0 = __uint_as_float(f2tf32(v0)); v1 = __uint_as_float(f2tf32(v1));
                    v2 = __uint_as_float(f2tf32(v2)); v3 = __uint_as_float(f2tf32(v3));
                }
                *reinterpret_cast<float2*>(&C[(size_t)r0 * DDIM + col]) = make_float2(v0, v1);
                *reinterpret_cast<float2*>(&C[(size_t)(r0 + 8) * DDIM + col]) = make_float2(v2, v3);
            }
        }
    }
}

// ---------------- flash attention: 256-row Q tile, register-resident fp16 P,
// ---------------- split fp16 V (hi+lo) via ldmatrix.trans, cp.async double-buffer ----------
#define AQT 256
#define ATHR 256
#define AP 68     // K/Q stride (floats): LDSM conflict-free
#define VPH 72    // V stride (halves): 144B rows -> trans-LDSM conflict-free
#define ASMEM ((2*64*AP + AQT*AP) * 4 + 2 * (2*64*VPH) * 2 + 2 * 64 * 4)

__global__ __launch_bounds__(ATHR, 1)
void attn_kernel(const float* __restrict__ Q, const float* __restrict__ K,
                 const __half* __restrict__ VH, const __half* __restrict__ VL,
                 const int* __restrict__ mask, float* __restrict__ O) {
    extern __shared__ uint32_t smem_u[];
    uint32_t* Ks0 = smem_u;                        // 2 stages x 64 rows (tf32 bits)
    __half* Vh0 = (__half*)(Ks0 + 2 * 64 * AP);    // 2 stages x 64 rows fp16 hi
    __half* Vl0 = Vh0 + 2 * 64 * VPH;              // 2 stages x 64 rows fp16 lo
    uint32_t* Ps = (uint32_t*)(Vl0 + 2 * 64 * VPH);// AQT rows (Q staging only)
    int* msk0 = (int*)(Ps + AQT * AP);

    const int qi = gridDim.x - 1 - blockIdx.x;     // heavy tiles first
    const int bh = blockIdx.y;
    const int b = bh / HH, h = bh % HH;

    const int tid = threadIdx.x;
    const int w = tid >> 5, lane = tid & 31;
    const int g = lane >> 2, tig = lane & 3;
    const int wrow = w * 32;

    const float* Qb = Q + ((size_t)b * SS + (size_t)qi * AQT) * DDIM + h * DKK;
    const float* Kb = K + (size_t)b * SS * DDIM + h * DKK;
    const __half* VHb = VH + (size_t)b * SS * DDIM + h * DKK;
    const __half* VLb = VL + (size_t)b * SS * DDIM + h * DKK;
    float* Ob = O + ((size_t)b * SS + (size_t)qi * AQT) * DDIM + h * DKK;

    const uint32_t sK = (uint32_t)__cvta_generic_to_shared(Ks0);
    const uint32_t sVh = (uint32_t)__cvta_generic_to_shared(Vh0);
    const uint32_t sVl = (uint32_t)__cvta_generic_to_shared(Vl0);
    const uint32_t sP = (uint32_t)__cvta_generic_to_shared(Ps);
    const uint32_t sM = (uint32_t)__cvta_generic_to_shared(msk0);

    const int lane7 = lane & 7;
    const int a_ro = ((lane >> 3) & 1) * 8;
    const int a_ko = ((lane >> 4) & 1) * 4;
    const int b_no = ((lane >> 4) & 1) * 8;
    const int b_ko = ((lane >> 3) & 1) * 4;
    // trans-ldsm address components for V (fp16): row within 16-k chunk, col half-offset
    const int v_ro = lane & 15;
    const int v_co = (lane >> 4) * 8;

    const float qscale = 0.125f * 1.4426950408889634f;

    auto issueKV = [&](int st, int kt) {
        const float* Kt = Kb + (size_t)kt * 64 * DDIM;
        const __half* VHt = VHb + (size_t)kt * 64 * DDIM;
        const __half* VLt = VLb + (size_t)kt * 64 * DDIM;
#pragma unroll
        for (int t = 0; t < 4; t++) {              // K: 1024 x 16B
            int i = tid + t * ATHR;
            int r = i >> 4;
            int c4 = (i & 15) << 2;
            cp16(sK + (uint32_t)((st * 64 + r) * AP + c4) * 4, Kt + (size_t)r * DDIM + c4);
        }
#pragma unroll
        for (int t = 0; t < 2; t++) {              // Vh: 512 x 16B, Vl: 512 x 16B
            int i = tid + t * ATHR;
            int r = i >> 3;
            int c8 = (i & 7) << 3;
            uint32_t off = (uint32_t)((st * 64 + r) * VPH + c8) * 2;
            cp16(sVh + off, VHt + (size_t)r * DDIM + c8);
            cp16(sVl + off, VLt + (size_t)r * DDIM + c8);
        }
        if (tid < 64) cp4(sM + (uint32_t)(st * 64 + tid) * 4, &mask[(size_t)b * SS + kt * 64 + tid]);
    };

    const int ktmax = (AQT / 64) * qi + (AQT / 64) - 1;   // 4*qi + 3
    issueKV(0, 0);
    cp_commit();

    // stage Q (AQT x 64), scale+round, then pull fragments via ldmatrix
#pragma unroll
    for (int t = 0; t < 16; t++) {
        int i = tid + t * ATHR;
        int r = i >> 4;
        int c4 = (i & 15) << 2;
        float4 v = *reinterpret_cast<const float4*>(Qb + (size_t)r * DDIM + c4);
        uint4 u = make_uint4(f2tf32(v.x * qscale), f2tf32(v.y * qscale),
                             f2tf32(v.z * qscale), f2tf32(v.w * qscale));
        *reinterpret_cast<uint4*>(&Ps[r * AP + c4]) = u;
    }
    __syncthreads();

    uint32_t qf[2][8][4];
#pragma unroll
    for (int mt = 0; mt < 2; mt++) {
        const uint32_t base = sP + (uint32_t)(((wrow + mt * 16 + a_ro + lane7) * AP + a_ko) * 4);
#pragma unroll
        for (int ks = 0; ks < 8; ks++)
            ldsm4(qf[mt][ks][0], qf[mt][ks][1], qf[mt][ks][2], qf[mt][ks][3],
                  base + (uint32_t)(ks * 32));
    }

    float mrow[2][2], lrow[2][2];
    float o[2][8][4];
#pragma unroll
    for (int mt = 0; mt < 2; mt++) {
        mrow[mt][0] = mrow[mt][1] = -1e30f;
        lrow[mt][0] = lrow[mt][1] = 0.f;
#pragma unroll
        for (int nt = 0; nt < 8; nt++)
#pragma unroll
            for (int e = 0; e < 4; e++) o[mt][nt][e] = 0.f;
    }

    const int rowmax = qi * AQT + wrow + 31;

    for (int kt = 0; kt <= ktmax; kt++) {
        const int cur = kt & 1;
        __syncthreads();
        if (kt < ktmax) {
            issueKV(cur ^ 1, kt + 1);
            cp_commit();
            cp_wait<1>();
        } else {
            cp_wait<0>();
        }
        __syncthreads();

        const uint32_t sKst = sK + (uint32_t)(cur * 64 * AP * 4);
        const uint32_t vH0 = sVh + (uint32_t)(cur * 64 * VPH * 2)
                           + (uint32_t)(v_ro * VPH + v_co) * 2;
        const uint32_t vL0 = sVl + (uint32_t)(cur * 64 * VPH * 2)
                           + (uint32_t)(v_ro * VPH + v_co) * 2;
        const int* msk = msk0 + cur * 64;

        if (kt * 64 > rowmax) continue;

        const int mvl0 = msk[lane], mvl1 = msk[32 + lane];
        const bool allvalid = __all_sync(0xffffffffu, (mvl0 != 0) && (mvl1 != 0));

        // S = Q @ K^T : 32x64 per warp (tf32)
        float s[2][8][4];
#pragma unroll
        for (int mt = 0; mt < 2; mt++)
#pragma unroll
            for (int nt = 0; nt < 8; nt++)
                s[mt][nt][0] = s[mt][nt][1] = s[mt][nt][2] = s[mt][nt][3] = 0.f;

        const uint32_t kb0 = sKst + (uint32_t)(((b_no + lane7) * AP + b_ko) * 4);
#pragma unroll
        for (int ks = 0; ks < 8; ks++) {
            const uint32_t ksB = (uint32_t)(ks * 32);
            uint32_t bf[8][2];
#pragma unroll
            for (int j = 0; j < 4; j++)
                ldsm4(bf[2*j][0], bf[2*j][1], bf[2*j+1][0], bf[2*j+1][1],
                      kb0 + (uint32_t)(j * 16 * AP * 4) + ksB);
#pragma unroll
            for (int mt = 0; mt < 2; mt++)
#pragma unroll
                for (int nt = 0; nt < 8; nt++)
                    mma_tf32(s[mt][nt], qf[mt][ks][0], qf[mt][ks][1],
                             qf[mt][ks][2], qf[mt][ks][3], bf[nt][0], bf[nt][1]);
        }

        // masking + online softmax; P packed to fp16 registers (no smem)
        uint32_t ph[2][8][2];
#pragma unroll
        for (int mt = 0; mt < 2; mt++) {
            const int q0 = qi * AQT + wrow + mt * 16 + g;
            const int q1 = q0 + 8;
            const bool needc = (kt * 64 + 63 > qi * AQT + wrow + mt * 16);

            if (!allvalid) {
#pragma unroll
                for (int nt = 0; nt < 8; nt++) {
                    int cl = nt * 8 + 2 * tig;
                    int cg = kt * 64 + cl;
                    bool mv0 = (msk[cl] != 0);
                    bool mv1 = (msk[cl + 1] != 0);
                    if (!mv0 || (needc && cg > q0))     s[mt][nt][0] = -1e30f;
                    if (!mv1 || (needc && cg + 1 > q0)) s[mt][nt][1] = -1e30f;
                    if (!mv0 || (needc && cg > q1))     s[mt][nt][2] = -1e30f;
                    if (!mv1 || (needc && cg + 1 > q1)) s[mt][nt][3] = -1e30f;
                }
            } else if (needc) {
#pragma unroll
                for (int nt = 0; nt < 8; nt++) {
                    int cg = kt * 64 + nt * 8 + 2 * tig;
                    if (cg > q0)     s[mt][nt][0] = -1e30f;
                    if (cg + 1 > q0) s[mt][nt][1] = -1e30f;
                    if (cg > q1)     s[mt][nt][2] = -1e30f;
                    if (cg + 1 > q1) s[mt][nt][3] = -1e30f;
                }
            }

            float rm0 = -1e30f, rm1 = -1e30f;
#pragma unroll
            for (int nt = 0; nt < 8; nt++) {
                rm0 = fmaxf(rm0, fmaxf(s[mt][nt][0], s[mt][nt][1]));
                rm1 = fmaxf(rm1, fmaxf(s[mt][nt][2], s[mt][nt][3]));
            }
            rm0 = fmaxf(rm0, __shfl_xor_sync(0xffffffffu, rm0, 1));
            rm0 = fmaxf(rm0, __shfl_xor_sync(0xffffffffu, rm0, 2));
            rm1 = fmaxf(rm1, __shfl_xor_sync(0xffffffffu, rm1, 1));
            rm1 = fmaxf(rm1, __shfl_xor_sync(0xffffffffu, rm1, 2));

            float mn0 = fmaxf(mrow[mt][0], rm0);
            float mn1 = fmaxf(mrow[mt][1], rm1);
            float al0 = ex2(mrow[mt][0] - mn0);
            float al1 = ex2(mrow[mt][1] - mn1);
            mrow[mt][0] = mn0; mrow[mt][1] = mn1;

            float rs0 = 0.f, rs1 = 0.f;
#pragma unroll
            for (int nt = 0; nt < 8; nt++) {
                float p0 = ex2(s[mt][nt][0] - mn0);
                float p1 = ex2(s[mt][nt][1] - mn0);
                float p2 = ex2(s[mt][nt][2] - mn1);
                float p3 = ex2(s[mt][nt][3] - mn1);
                rs0 += p0 + p1;
                rs1 += p2 + p3;
                ph[mt][nt][0] = packh2(p0, p1);   // row g
                ph[mt][nt][1] = packh2(p2, p3);   // row g+8
            }
            rs0 += __shfl_xor_sync(0xffffffffu, rs0, 1);
            rs0 += __shfl_xor_sync(0xffffffffu, rs0, 2);
            rs1 += __shfl_xor_sync(0xffffffffu, rs1, 1);
            rs1 += __shfl_xor_sync(0xffffffffu, rs1, 2);
            lrow[mt][0] = lrow[mt][0] * al0 + rs0;
            lrow[mt][1] = lrow[mt][1] * al1 + rs1;

#pragma unroll
            for (int nt = 0; nt < 8; nt++) {
                o[mt][nt][0] *= al0; o[mt][nt][1] *= al0;
                o[mt][nt][2] *= al1; o[mt][nt][3] *= al1;
            }
        }

        // O += P @ (Vhi + Vlo), fp16 m16n8k16, P in registers, V via ldmatrix.trans
#pragma unroll
        for (int j = 0; j < 4; j++) {              // k-steps of 16 keys
            const uint32_t jb = (uint32_t)(j * 16 * VPH * 2);
            uint32_t vf[8][2];
            // hi part
#pragma unroll
            for (int dgi = 0; dgi < 4; dgi++)
                ldsm4t(vf[2*dgi][0], vf[2*dgi][1], vf[2*dgi+1][0], vf[2*dgi+1][1],
                       vH0 + jb + (uint32_t)(dgi * 32));
#pragma unroll
            for (int mt = 0; mt < 2; mt++) {
                uint32_t a0 = ph[mt][2*j][0],   a1 = ph[mt][2*j][1];
                uint32_t a2 = ph[mt][2*j+1][0], a3 = ph[mt][2*j+1][1];
#pragma unroll
                for (int nt = 0; nt < 8; nt++)
                    mma_f16(o[mt][nt], a0, a1, a2, a3, vf[nt][0], vf[nt][1]);
            }
            // lo part
#pragma unroll
            for (int dgi = 0; dgi < 4; dgi++)
                ldsm4t(vf[2*dgi][0], vf[2*dgi][1], vf[2*dgi+1][0], vf[2*dgi+1][1],
                       vL0 + jb + (uint32_t)(dgi * 32));
#pragma unroll
            for (int mt = 0; mt < 2; mt++) {
                uint32_t a0 = ph[mt][2*j][0],   a1 = ph[mt][2*j][1];
                uint32_t a2 = ph[mt][2*j+1][0], a3 = ph[mt][2*j+1][1];
#pragma unroll
                for (int nt = 0; nt < 8; nt++)
                    mma_f16(o[mt][nt], a0, a1, a2, a3, vf[nt][0], vf[nt][1]);
            }
        }
    }

    // normalize + store (rounded: feeds the Wo tf32 GEMM)
#pragma unroll
    for (int mt = 0; mt < 2; mt++) {
        float i0 = 1.f / lrow[mt][0];
        float i1 = 1.f / lrow[mt][1];
        int r0 = wrow + mt * 16 + g;
#pragma unroll
        for (int nt = 0; nt < 8; nt++) {
            int cl = nt * 8 + 2 * tig;
            *reinterpret_cast<float2*>(&Ob[(size_t)r0 * DDIM + cl]) =
                make_float2(__uint_as_float(f2tf32(o[mt][nt][0] * i0)),
                            __uint_as_float(f2tf32(o[mt][nt][1] * i0)));
            *reinterpret_cast<float2*>(&Ob[(size_t)(r0 + 8) * DDIM + cl]) =
                make_float2(__uint_as_float(f2tf32(o[mt][nt][2] * i1)),
                            __uint_as_float(f2tf32(o[mt][nt][3] * i1)));
        }
    }
}

// ---------------- launch ----------------
extern "C" void kernel_launch(void* const* d_in, const int* in_sizes, int n_in,
                              void* d_out, int out_size) {
    const float* xq = (const float*)d_in[0];
    const float* xk = (const float*)d_in[1];
    const float* xv = (const float*)d_in[2];
    const int* mask = (const int*)d_in[3];
    const float* Wq = (const float*)d_in[4];
    const float* Wk = (const float*)d_in[5];
    const float* Wv = (const float*)d_in[6];
    const float* Wo = (const float*)d_in[7];
    float* out = (float*)d_out;

    float *Qp, *Kp, *Ap;
    __half *VHp, *VLp;
    cudaGetSymbolAddress((void**)&Qp, g_Q);
    cudaGetSymbolAddress((void**)&Kp, g_K);
    cudaGetSymbolAddress((void**)&Ap, g_A);
    cudaGetSymbolAddress((void**)&VHp, g_Vh);
    cudaGetSymbolAddress((void**)&VLp, g_Vl);

    cudaFuncSetAttribute(gemm_nt, cudaFuncAttributeMaxDynamicSharedMemorySize, GSMEM);
    cudaFuncSetAttribute(attn_kernel, cudaFuncAttributeMaxDynamicSharedMemorySize, ASMEM);

    // fused QKV projections; Q/K rounded fp32, V written as fp16 hi+lo
    gemm_nt<<<dim3(DDIM / GBN, MTOT / GBM, 3), 256, GSMEM>>>(
        xq, xk, xv, Wq, Wk, Wv, Qp, Kp, Ap, VHp, VLp, 1, 1);

    attn_kernel<<<dim3(SS / AQT, BB * HH), ATHR, ASMEM>>>(Qp, Kp, VHp, VLp, mask, Ap);

    // output projection; exact fp32 output
    gemm_nt<<<dim3(DDIM / GBN, MTOT / GBM, 1), 256, GSMEM>>>(
        Ap, Ap, Ap, Wo, Wo, Wo, out, out, out, VHp, VLp, 0, 0);
}

// round 11
// speedup vs baseline: 1.1066x; 1.0847x over previous
#include <cuda_runtime.h>
#include <cuda_fp16.h>
#include <cstdint>

#define BB 4
#define SS 2048
#define DDIM 1024
#define HH 16
#define DKK 64
#define MTOT (BB*SS)   // 8192

// ---------------- scratch (static __device__, allocation-free) ----------------
__device__ float g_Q[(size_t)MTOT*DDIM];
__device__ float g_K[(size_t)MTOT*DDIM];
__device__ float g_A[(size_t)MTOT*DDIM];
__device__ __half g_Vh[(size_t)MTOT*DDIM];

// ---------------- helpers ----------------
__device__ __forceinline__ uint32_t f2tf32(float f) {
    uint32_t u;
    asm("cvt.rna.tf32.f32 %0, %1;" : "=r"(u) : "f"(f));
    return u;
}
__device__ __forceinline__ uint32_t bits2tf32(uint32_t b) {
    return f2tf32(__uint_as_float(b));
}
__device__ __forceinline__ float ex2(float x) {
    float y;
    asm("ex2.approx.ftz.f32 %0, %1;" : "=f"(y) : "f"(x));
    return y;
}
__device__ __forceinline__ uint32_t packh2(float lo, float hi) {
    __half2 h = __floats2half2_rn(lo, hi);   // x (low) = lo, y (high) = hi
    return *reinterpret_cast<uint32_t*>(&h);
}
__device__ __forceinline__ void cp16(uint32_t saddr, const void* g) {
    asm volatile("cp.async.cg.shared.global [%0], [%1], 16;" :: "r"(saddr), "l"(g));
}
__device__ __forceinline__ void cp4(uint32_t saddr, const void* g) {
    asm volatile("cp.async.ca.shared.global [%0], [%1], 4;" :: "r"(saddr), "l"(g));
}
__device__ __forceinline__ void cp_commit() {
    asm volatile("cp.async.commit_group;");
}
template <int N>
__device__ __forceinline__ void cp_wait() {
    asm volatile("cp.async.wait_group %0;" :: "n"(N));
}
__device__ __forceinline__ void ldsm4(uint32_t& r0, uint32_t& r1, uint32_t& r2, uint32_t& r3,
                                      uint32_t addr) {
    asm volatile("ldmatrix.sync.aligned.m8n8.x4.shared.b16 {%0,%1,%2,%3}, [%4];"
                 : "=r"(r0), "=r"(r1), "=r"(r2), "=r"(r3) : "r"(addr));
}
__device__ __forceinline__ void ldsm4t(uint32_t& r0, uint32_t& r1, uint32_t& r2, uint32_t& r3,
                                       uint32_t addr) {
    asm volatile("ldmatrix.sync.aligned.m8n8.x4.trans.shared.b16 {%0,%1,%2,%3}, [%4];"
                 : "=r"(r0), "=r"(r1), "=r"(r2), "=r"(r3) : "r"(addr));
}

// D(16x8,f32) += A(16x8,tf32,row) * B(8x8,tf32,col)
__device__ __forceinline__ void mma_tf32(float c[4],
                                         uint32_t a0, uint32_t a1, uint32_t a2, uint32_t a3,
                                         uint32_t b0, uint32_t b1) {
    asm volatile(
        "mma.sync.aligned.m16n8k8.row.col.f32.tf32.tf32.f32 "
        "{%0,%1,%2,%3}, {%4,%5,%6,%7}, {%8,%9}, {%0,%1,%2,%3};"
        : "+f"(c[0]), "+f"(c[1]), "+f"(c[2]), "+f"(c[3])
        : "r"(a0), "r"(a1), "r"(a2), "r"(a3), "r"(b0), "r"(b1));
}
// D(16x8,f32) += A(16x16,f16,row) * B(16x8,f16,col)
__device__ __forceinline__ void mma_f16(float c[4],
                                        uint32_t a0, uint32_t a1, uint32_t a2, uint32_t a3,
                                        uint32_t b0, uint32_t b1) {
    asm volatile(
        "mma.sync.aligned.m16n8k16.row.col.f32.f16.f16.f32 "
        "{%0,%1,%2,%3}, {%4,%5,%6,%7}, {%8,%9}, {%0,%1,%2,%3};"
        : "+f"(c[0]), "+f"(c[1]), "+f"(c[2]), "+f"(c[3])
        : "r"(a0), "r"(a1), "r"(a2), "r"(a3), "r"(b0), "r"(b1));
}

// ---------------- GEMM: C[m][n] = sum_k A[m][k] * W[n][k] (R7 proven config) ----------------
#define GBM 128
#define GBN 128
#define GBK 32
#define GST (GBK + 4)
#define GSTG (GBM * GST)
#define GNS 3
#define GSMEM (2 * GNS * GSTG * 4)            // 110592 B

__global__ __launch_bounds__(256, 2)
void gemm_nt(const float* __restrict__ A0, const float* __restrict__ A1, const float* __restrict__ A2,
             const float* __restrict__ W0, const float* __restrict__ W1, const float* __restrict__ W2,
             float* __restrict__ C0, float* __restrict__ C1, float* __restrict__ C2,
             __half* __restrict__ VH,
             int roundOut, int vhalf) {
    extern __shared__ float gsm[];
    float* Asm = gsm;
    float* Bsm = gsm + GNS * GSTG;

    const int z = blockIdx.z;
    const float* A = (z == 0) ? A0 : (z == 1) ? A1 : A2;
    const float* W = (z == 0) ? W0 : (z == 1) ? W1 : W2;
    float*       C = (z == 0) ? C0 : (z == 1) ? C1 : C2;

    const int m0 = blockIdx.y * GBM;
    const int n0 = blockIdx.x * GBN;
    const int tid = threadIdx.x;
    const int w = tid >> 5, lane = tid & 31;
    const int g = lane >> 2, tig = lane & 3;
    const int wm = (w >> 2) * 64;
    const int wn = (w & 3) * 32;

    const int lr = tid >> 3;
    const int lc = (tid & 7) << 2;

    const uint32_t sA = (uint32_t)__cvta_generic_to_shared(Asm);
    const uint32_t sB = (uint32_t)__cvta_generic_to_shared(Bsm);

    const int lane7 = lane & 7;
    const int a_ro = ((lane >> 3) & 1) * 8;
    const int a_ko = ((lane >> 4) & 1) * 4;
    const int b_no = ((lane >> 4) & 1) * 8;
    const int b_ko = ((lane >> 3) & 1) * 4;

    uint32_t aIdx[4];
#pragma unroll
    for (int mt = 0; mt < 4; mt++)
        aIdx[mt] = (uint32_t)(((wm + mt * 16 + a_ro + lane7) * GST + a_ko) * 4);
    const uint32_t bIdx = (uint32_t)(((wn + b_no + lane7) * GST + b_ko) * 4);

    float acc[4][4][4];
#pragma unroll
    for (int i = 0; i < 4; i++)
#pragma unroll
        for (int j = 0; j < 4; j++)
#pragma unroll
            for (int e = 0; e < 4; e++) acc[i][j][e] = 0.f;

    auto issue = [&](int st, int k0) {
#pragma unroll
        for (int it = 0; it < 4; it++) {
            int row = lr + it * 32;
            cp16(sA + (uint32_t)((st * GBM + row) * GST + lc) * 4,
                 &A[(size_t)(m0 + row) * DDIM + k0 + lc]);
            cp16(sB + (uint32_t)((st * GBN + row) * GST + lc) * 4,
                 &W[(size_t)(n0 + row) * DDIM + k0 + lc]);
        }
    };

    issue(0, 0); cp_commit();
    issue(1, GBK); cp_commit();

    const int NKT = DDIM / GBK;
    for (int kt = 0; kt < NKT; kt++) {
        if (kt < NKT - 1) cp_wait<1>(); else cp_wait<0>();
        __syncthreads();

        const int st = kt % GNS;
        const uint32_t stb = (uint32_t)(st * GSTG * 4);

#pragma unroll
        for (int ks = 0; ks < 4; ks++) {
            const uint32_t ksB = (uint32_t)(ks * 32);
            uint32_t b[4][2];
            uint32_t bb = sB + stb + bIdx + ksB;
            ldsm4(b[0][0], b[0][1], b[1][0], b[1][1], bb);
            ldsm4(b[2][0], b[2][1], b[3][0], b[3][1], bb + 16 * GST * 4);
            uint32_t a[4][4];
#pragma unroll
            for (int mt = 0; mt < 4; mt++)
                ldsm4(a[mt][0], a[mt][1], a[mt][2], a[mt][3], sA + stb + aIdx[mt] + ksB);

#pragma unroll
            for (int nt = 0; nt < 4; nt++) {
                b[nt][0] = bits2tf32(b[nt][0]);
                b[nt][1] = bits2tf32(b[nt][1]);
            }
#pragma unroll
            for (int mt = 0; mt < 4; mt++) {
#pragma unroll
                for (int e = 0; e < 4; e++) a[mt][e] = bits2tf32(a[mt][e]);
#pragma unroll
                for (int nt = 0; nt < 4; nt++)
                    mma_tf32(acc[mt][nt], a[mt][0], a[mt][1], a[mt][2], a[mt][3],
                             b[nt][0], b[nt][1]);
            }
        }

        if (kt + 2 < NKT) {
            issue((kt + 2) % GNS, (kt + 2) * GBK);
            cp_commit();
        }
    }

    const bool toHalf = (vhalf != 0) && (z == 2);
#pragma unroll
    for (int mt = 0; mt < 4; mt++) {
        int r0 = m0 + wm + mt * 16 + g;
#pragma unroll
        for (int nt = 0; nt < 4; nt++) {
            int col = n0 + wn + nt * 8 + 2 * tig;
            float v0 = acc[mt][nt][0], v1 = acc[mt][nt][1];
            float v2 = acc[mt][nt][2], v3 = acc[mt][nt][3];
            if (toHalf) {
                *reinterpret_cast<__half2*>(&VH[(size_t)r0 * DDIM + col]) =
                    __floats2half2_rn(v0, v1);
                *reinterpret_cast<__half2*>(&VH[(size_t)(r0 + 8) * DDIM + col]) =
                    __floats2half2_rn(v2, v3);
            } else {
                if (roundOut) {
                    v0 = __uint_as_float(f2tf32(v0)); v1 = __uint_as_float(f2tf32(v1));
                    v2 = __uint_as_float(f2tf32(v2)); v3 = __uint_as_float(f2tf32(v3));
                }
                *reinterpret_cast<float2*>(&C[(size_t)r0 * DDIM + col]) = make_float2(v0, v1);
                *reinterpret_cast<float2*>(&C[(size_t)(r0 + 8) * DDIM + col]) = make_float2(v2, v3);
            }
        }
    }
}

// ---------------- flash attention: 256-row Q tile, register-resident fp16 P,
// ---------------- single fp16 V via ldmatrix.trans, cp.async double-buffer ----------
#define AQT 256
#define ATHR 256
#define AP 68     // K/Q stride (floats): LDSM conflict-free
#define VPH 72    // V stride (halves): 144B rows -> trans-LDSM conflict-free
#define ASMEM ((2*64*AP + AQT*AP) * 4 + (2*64*VPH) * 2 + 2 * 64 * 4)   // 123392 B

__global__ __launch_bounds__(ATHR, 1)
void attn_kernel(const float* __restrict__ Q, const float* __restrict__ K,
                 const __half* __restrict__ VH,
                 const int* __restrict__ mask, float* __restrict__ O) {
    extern __shared__ uint32_t smem_u[];
    uint32_t* Ks0 = smem_u;                        // 2 stages x 64 rows (tf32 bits)
    __half* Vh0 = (__half*)(Ks0 + 2 * 64 * AP);    // 2 stages x 64 rows fp16
    uint32_t* Ps = (uint32_t*)(Vh0 + 2 * 64 * VPH);// AQT rows (Q staging only)
    int* msk0 = (int*)(Ps + AQT * AP);

    const int qi = gridDim.x - 1 - blockIdx.x;     // heavy tiles first
    const int bh = blockIdx.y;
    const int b = bh / HH, h = bh % HH;

    const int tid = threadIdx.x;
    const int w = tid >> 5, lane = tid & 31;
    const int g = lane >> 2, tig = lane & 3;
    const int wrow = w * 32;

    const float* Qb = Q + ((size_t)b * SS + (size_t)qi * AQT) * DDIM + h * DKK;
    const float* Kb = K + (size_t)b * SS * DDIM + h * DKK;
    const __half* VHb = VH + (size_t)b * SS * DDIM + h * DKK;
    float* Ob = O + ((size_t)b * SS + (size_t)qi * AQT) * DDIM + h * DKK;

    const uint32_t sK = (uint32_t)__cvta_generic_to_shared(Ks0);
    const uint32_t sVh = (uint32_t)__cvta_generic_to_shared(Vh0);
    const uint32_t sP = (uint32_t)__cvta_generic_to_shared(Ps);
    const uint32_t sM = (uint32_t)__cvta_generic_to_shared(msk0);

    const int lane7 = lane & 7;
    const int a_ro = ((lane >> 3) & 1) * 8;
    const int a_ko = ((lane >> 4) & 1) * 4;
    const int b_no = ((lane >> 4) & 1) * 8;
    const int b_ko = ((lane >> 3) & 1) * 4;
    // trans-ldsm address components for V (fp16)
    const int v_ro = lane & 15;
    const int v_co = (lane >> 4) * 8;

    const float qscale = 0.125f * 1.4426950408889634f;

    auto issueKV = [&](int st, int kt) {
        const float* Kt = Kb + (size_t)kt * 64 * DDIM;
        const __half* VHt = VHb + (size_t)kt * 64 * DDIM;
#pragma unroll
        for (int t = 0; t < 4; t++) {              // K: 1024 x 16B
            int i = tid + t * ATHR;
            int r = i >> 4;
            int c4 = (i & 15) << 2;
            cp16(sK + (uint32_t)((st * 64 + r) * AP + c4) * 4, Kt + (size_t)r * DDIM + c4);
        }
#pragma unroll
        for (int t = 0; t < 2; t++) {              // V: 512 x 16B
            int i = tid + t * ATHR;
            int r = i >> 3;
            int c8 = (i & 7) << 3;
            cp16(sVh + (uint32_t)((st * 64 + r) * VPH + c8) * 2, VHt + (size_t)r * DDIM + c8);
        }
        if (tid < 64) cp4(sM + (uint32_t)(st * 64 + tid) * 4, &mask[(size_t)b * SS + kt * 64 + tid]);
    };

    const int ktmax = (AQT / 64) * qi + (AQT / 64) - 1;   // 4*qi + 3
    issueKV(0, 0);
    cp_commit();

    // stage Q (AQT x 64), scale+round, then pull fragments via ldmatrix
#pragma unroll
    for (int t = 0; t < 16; t++) {
        int i = tid + t * ATHR;
        int r = i >> 4;
        int c4 = (i & 15) << 2;
        float4 v = *reinterpret_cast<const float4*>(Qb + (size_t)r * DDIM + c4);
        uint4 u = make_uint4(f2tf32(v.x * qscale), f2tf32(v.y * qscale),
                             f2tf32(v.z * qscale), f2tf32(v.w * qscale));
        *reinterpret_cast<uint4*>(&Ps[r * AP + c4]) = u;
    }
    __syncthreads();

    uint32_t qf[2][8][4];
#pragma unroll
    for (int mt = 0; mt < 2; mt++) {
        const uint32_t base = sP + (uint32_t)(((wrow + mt * 16 + a_ro + lane7) * AP + a_ko) * 4);
#pragma unroll
        for (int ks = 0; ks < 8; ks++)
            ldsm4(qf[mt][ks][0], qf[mt][ks][1], qf[mt][ks][2], qf[mt][ks][3],
                  base + (uint32_t)(ks * 32));
    }

    float mrow[2][2], lrow[2][2];
    float o[2][8][4];
#pragma unroll
    for (int mt = 0; mt < 2; mt++) {
        mrow[mt][0] = mrow[mt][1] = -1e30f;
        lrow[mt][0] = lrow[mt][1] = 0.f;
#pragma unroll
        for (int nt = 0; nt < 8; nt++)
#pragma unroll
            for (int e = 0; e < 4; e++) o[mt][nt][e] = 0.f;
    }

    const int rowmax = qi * AQT + wrow + 31;

    for (int kt = 0; kt <= ktmax; kt++) {
        const int cur = kt & 1;
        __syncthreads();
        if (kt < ktmax) {
            issueKV(cur ^ 1, kt + 1);
            cp_commit();
            cp_wait<1>();
        } else {
            cp_wait<0>();
        }
        __syncthreads();

        const uint32_t sKst = sK + (uint32_t)(cur * 64 * AP * 4);
        const uint32_t vH0 = sVh + (uint32_t)(cur * 64 * VPH * 2)
                           + (uint32_t)(v_ro * VPH + v_co) * 2;
        const int* msk = msk0 + cur * 64;

        if (kt * 64 > rowmax) continue;

        const int mvl0 = msk[lane], mvl1 = msk[32 + lane];
        const bool allvalid = __all_sync(0xffffffffu, (mvl0 != 0) && (mvl1 != 0));

        // S = Q @ K^T : 32x64 per warp (tf32)
        float s[2][8][4];
#pragma unroll
        for (int mt = 0; mt < 2; mt++)
#pragma unroll
            for (int nt = 0; nt < 8; nt++)
                s[mt][nt][0] = s[mt][nt][1] = s[mt][nt][2] = s[mt][nt][3] = 0.f;

        const uint32_t kb0 = sKst + (uint32_t)(((b_no + lane7) * AP + b_ko) * 4);
#pragma unroll
        for (int ks = 0; ks < 8; ks++) {
            const uint32_t ksB = (uint32_t)(ks * 32);
            uint32_t bf[8][2];
#pragma unroll
            for (int j = 0; j < 4; j++)
                ldsm4(bf[2*j][0], bf[2*j][1], bf[2*j+1][0], bf[2*j+1][1],
                      kb0 + (uint32_t)(j * 16 * AP * 4) + ksB);
#pragma unroll
            for (int mt = 0; mt < 2; mt++)
#pragma unroll
                for (int nt = 0; nt < 8; nt++)
                    mma_tf32(s[mt][nt], qf[mt][ks][0], qf[mt][ks][1],
                             qf[mt][ks][2], qf[mt][ks][3], bf[nt][0], bf[nt][1]);
        }

        // masking + online softmax; P packed to fp16 registers (no smem)
        uint32_t ph[2][8][2];
#pragma unroll
        for (int mt = 0; mt < 2; mt++) {
            const int q0 = qi * AQT + wrow + mt * 16 + g;
            const int q1 = q0 + 8;
            const bool needc = (kt * 64 + 63 > qi * AQT + wrow + mt * 16);

            if (!allvalid) {
#pragma unroll
                for (int nt = 0; nt < 8; nt++) {
                    int cl = nt * 8 + 2 * tig;
                    int cg = kt * 64 + cl;
                    bool mv0 = (msk[cl] != 0);
                    bool mv1 = (msk[cl + 1] != 0);
                    if (!mv0 || (needc && cg > q0))     s[mt][nt][0] = -1e30f;
                    if (!mv1 || (needc && cg + 1 > q0)) s[mt][nt][1] = -1e30f;
                    if (!mv0 || (needc && cg > q1))     s[mt][nt][2] = -1e30f;
                    if (!mv1 || (needc && cg + 1 > q1)) s[mt][nt][3] = -1e30f;
                }
            } else if (needc) {
#pragma unroll
                for (int nt = 0; nt < 8; nt++) {
                    int cg = kt * 64 + nt * 8 + 2 * tig;
                    if (cg > q0)     s[mt][nt][0] = -1e30f;
                    if (cg + 1 > q0) s[mt][nt][1] = -1e30f;
                    if (cg > q1)     s[mt][nt][2] = -1e30f;
                    if (cg + 1 > q1) s[mt][nt][3] = -1e30f;
                }
            }

            float rm0 = -1e30f, rm1 = -1e30f;
#pragma unroll
            for (int nt = 0; nt < 8; nt++) {
                rm0 = fmaxf(rm0, fmaxf(s[mt][nt][0], s[mt][nt][1]));
                rm1 = fmaxf(rm1, fmaxf(s[mt][nt][2], s[mt][nt][3]));
            }
            rm0 = fmaxf(rm0, __shfl_xor_sync(0xffffffffu, rm0, 1));
            rm0 = fmaxf(rm0, __shfl_xor_sync(0xffffffffu, rm0, 2));
            rm1 = fmaxf(rm1, __shfl_xor_sync(0xffffffffu, rm1, 1));
            rm1 = fmaxf(rm1, __shfl_xor_sync(0xffffffffu, rm1, 2));

            float mn0 = fmaxf(mrow[mt][0], rm0);
            float mn1 = fmaxf(mrow[mt][1], rm1);
            float al0 = ex2(mrow[mt][0] - mn0);
            float al1 = ex2(mrow[mt][1] - mn1);
            mrow[mt][0] = mn0; mrow[mt][1] = mn1;

            float rs0 = 0.f, rs1 = 0.f;
#pragma unroll
            for (int nt = 0; nt < 8; nt++) {
                float p0 = ex2(s[mt][nt][0] - mn0);
                float p1 = ex2(s[mt][nt][1] - mn0);
                float p2 = ex2(s[mt][nt][2] - mn1);
                float p3 = ex2(s[mt][nt][3] - mn1);
                rs0 += p0 + p1;
                rs1 += p2 + p3;
                ph[mt][nt][0] = packh2(p0, p1);   // row g
                ph[mt][nt][1] = packh2(p2, p3);   // row g+8
            }
            rs0 += __shfl_xor_sync(0xffffffffu, rs0, 1);
            rs0 += __shfl_xor_sync(0xffffffffu, rs0, 2);
            rs1 += __shfl_xor_sync(0xffffffffu, rs1, 1);
            rs1 += __shfl_xor_sync(0xffffffffu, rs1, 2);
            lrow[mt][0] = lrow[mt][0] * al0 + rs0;
            lrow[mt][1] = lrow[mt][1] * al1 + rs1;

#pragma unroll
            for (int nt = 0; nt < 8; nt++) {
                o[mt][nt][0] *= al0; o[mt][nt][1] *= al0;
                o[mt][nt][2] *= al1; o[mt][nt][3] *= al1;
            }
        }

        // O += P @ V, fp16 m16n8k16, P in registers, V via ldmatrix.trans
#pragma unroll
        for (int j = 0; j < 4; j++) {              // k-steps of 16 keys
            const uint32_t jb = (uint32_t)(j * 16 * VPH * 2);
            uint32_t vf[8][2];
#pragma unroll
            for (int dgi = 0; dgi < 4; dgi++)
                ldsm4t(vf[2*dgi][0], vf[2*dgi][1], vf[2*dgi+1][0], vf[2*dgi+1][1],
                       vH0 + jb + (uint32_t)(dgi * 32));
#pragma unroll
            for (int mt = 0; mt < 2; mt++) {
                uint32_t a0 = ph[mt][2*j][0],   a1 = ph[mt][2*j][1];
                uint32_t a2 = ph[mt][2*j+1][0], a3 = ph[mt][2*j+1][1];
#pragma unroll
                for (int nt = 0; nt < 8; nt++)
                    mma_f16(o[mt][nt], a0, a1, a2, a3, vf[nt][0], vf[nt][1]);
            }
        }
    }

    // normalize + store (rounded: feeds the Wo tf32 GEMM)
#pragma unroll
    for (int mt = 0; mt < 2; mt++) {
        float i0 = 1.f / lrow[mt][0];
        float i1 = 1.f / lrow[mt][1];
        int r0 = wrow + mt * 16 + g;
#pragma unroll
        for (int nt = 0; nt < 8; nt++) {
            int cl = nt * 8 + 2 * tig;
            *reinterpret_cast<float2*>(&Ob[(size_t)r0 * DDIM + cl]) =
                make_float2(__uint_as_float(f2tf32(o[mt][nt][0] * i0)),
                            __uint_as_float(f2tf32(o[mt][nt][1] * i0)));
            *reinterpret_cast<float2*>(&Ob[(size_t)(r0 + 8) * DDIM + cl]) =
                make_float2(__uint_as_float(f2tf32(o[mt][nt][2] * i1)),
                            __uint_as_float(f2tf32(o[mt][nt][3] * i1)));
        }
    }
}

// ---------------- launch ----------------
extern "C" void kernel_launch(void* const* d_in, const int* in_sizes, int n_in,
                              void* d_out, int out_size) {
    const float* xq = (const float*)d_in[0];
    const float* xk = (const float*)d_in[1];
    const float* xv = (const float*)d_in[2];
    const int* mask = (const int*)d_in[3];
    const float* Wq = (const float*)d_in[4];
    const float* Wk = (const float*)d_in[5];
    const float* Wv = (const float*)d_in[6];
    const float* Wo = (const float*)d_in[7];
    float* out = (float*)d_out;

    float *Qp, *Kp, *Ap;
    __half *VHp;
    cudaGetSymbolAddress((void**)&Qp, g_Q);
    cudaGetSymbolAddress((void**)&Kp, g_K);
    cudaGetSymbolAddress((void**)&Ap, g_A);
    cudaGetSymbolAddress((void**)&VHp, g_Vh);

    cudaFuncSetAttribute(gemm_nt, cudaFuncAttributeMaxDynamicSharedMemorySize, GSMEM);
    cudaFuncSetAttribute(attn_kernel, cudaFuncAttributeMaxDynamicSharedMemorySize, ASMEM);

    // fused QKV projections; Q/K rounded fp32, V written as fp16
    gemm_nt<<<dim3(DDIM / GBN, MTOT / GBM, 3), 256, GSMEM>>>(
        xq, xk, xv, Wq, Wk, Wv, Qp, Kp, Ap, VHp, 1, 1);

    attn_kernel<<<dim3(SS / AQT, BB * HH), ATHR, ASMEM>>>(Qp, Kp, VHp, mask, Ap);

    // output projection; exact fp32 output
    gemm_nt<<<dim3(DDIM / GBN, MTOT / GBM, 1), 256, GSMEM>>>(
        Ap, Ap, Ap, Wo, Wo, Wo, out, out, out, VHp, 0, 0);
}

// round 12
// speedup vs baseline: 1.2295x; 1.1110x over previous
#include <cuda_runtime.h>
#include <cuda_fp16.h>
#include <cstdint>

#define BB 4
#define SS 2048
#define DDIM 1024
#define HH 16
#define DKK 64
#define MTOT (BB*SS)   // 8192

// ---------------- scratch (static __device__, allocation-free) ----------------
__device__ __half g_Qh[(size_t)MTOT*DDIM];
__device__ __half g_Kh[(size_t)MTOT*DDIM];
__device__ __half g_Vh[(size_t)MTOT*DDIM];
__device__ float  g_A[(size_t)MTOT*DDIM];

// ---------------- helpers ----------------
__device__ __forceinline__ uint32_t f2tf32(float f) {
    uint32_t u;
    asm("cvt.rna.tf32.f32 %0, %1;" : "=r"(u) : "f"(f));
    return u;
}
__device__ __forceinline__ uint32_t bits2tf32(uint32_t b) {
    return f2tf32(__uint_as_float(b));
}
__device__ __forceinline__ float ex2(float x) {
    float y;
    asm("ex2.approx.ftz.f32 %0, %1;" : "=f"(y) : "f"(x));
    return y;
}
__device__ __forceinline__ uint32_t packh2(float lo, float hi) {
    __half2 h = __floats2half2_rn(lo, hi);
    return *reinterpret_cast<uint32_t*>(&h);
}
__device__ __forceinline__ void cp16(uint32_t saddr, const void* g) {
    asm volatile("cp.async.cg.shared.global [%0], [%1], 16;" :: "r"(saddr), "l"(g));
}
__device__ __forceinline__ void cp4(uint32_t saddr, const void* g) {
    asm volatile("cp.async.ca.shared.global [%0], [%1], 4;" :: "r"(saddr), "l"(g));
}
__device__ __forceinline__ void cp_commit() {
    asm volatile("cp.async.commit_group;");
}
template <int N>
__device__ __forceinline__ void cp_wait() {
    asm volatile("cp.async.wait_group %0;" :: "n"(N));
}
__device__ __forceinline__ void ldsm4(uint32_t& r0, uint32_t& r1, uint32_t& r2, uint32_t& r3,
                                      uint32_t addr) {
    asm volatile("ldmatrix.sync.aligned.m8n8.x4.shared.b16 {%0,%1,%2,%3}, [%4];"
                 : "=r"(r0), "=r"(r1), "=r"(r2), "=r"(r3) : "r"(addr));
}
__device__ __forceinline__ void ldsm4t(uint32_t& r0, uint32_t& r1, uint32_t& r2, uint32_t& r3,
                                       uint32_t addr) {
    asm volatile("ldmatrix.sync.aligned.m8n8.x4.trans.shared.b16 {%0,%1,%2,%3}, [%4];"
                 : "=r"(r0), "=r"(r1), "=r"(r2), "=r"(r3) : "r"(addr));
}

// D(16x8,f32) += A(16x8,tf32,row) * B(8x8,tf32,col)
__device__ __forceinline__ void mma_tf32(float c[4],
                                         uint32_t a0, uint32_t a1, uint32_t a2, uint32_t a3,
                                         uint32_t b0, uint32_t b1) {
    asm volatile(
        "mma.sync.aligned.m16n8k8.row.col.f32.tf32.tf32.f32 "
        "{%0,%1,%2,%3}, {%4,%5,%6,%7}, {%8,%9}, {%0,%1,%2,%3};"
        : "+f"(c[0]), "+f"(c[1]), "+f"(c[2]), "+f"(c[3])
        : "r"(a0), "r"(a1), "r"(a2), "r"(a3), "r"(b0), "r"(b1));
}
// D(16x8,f32) += A(16x16,f16,row) * B(16x8,f16,col)
__device__ __forceinline__ void mma_f16(float c[4],
                                        uint32_t a0, uint32_t a1, uint32_t a2, uint32_t a3,
                                        uint32_t b0, uint32_t b1) {
    asm volatile(
        "mma.sync.aligned.m16n8k16.row.col.f32.f16.f16.f32 "
        "{%0,%1,%2,%3}, {%4,%5,%6,%7}, {%8,%9}, {%0,%1,%2,%3};"
        : "+f"(c[0]), "+f"(c[1]), "+f"(c[2]), "+f"(c[3])
        : "r"(a0), "r"(a1), "r"(a2), "r"(a3), "r"(b0), "r"(b1));
}

// ---------------- GEMM: C[m][n] = sum_k A[m][k] * W[n][k] (R7 proven config) ----------------
#define GBM 128
#define GBN 128
#define GBK 32
#define GST (GBK + 4)
#define GSTG (GBM * GST)
#define GNS 3
#define GSMEM (2 * GNS * GSTG * 4)            // 110592 B

__global__ __launch_bounds__(256, 2)
void gemm_nt(const float* __restrict__ A0, const float* __restrict__ A1, const float* __restrict__ A2,
             const float* __restrict__ W0, const float* __restrict__ W1, const float* __restrict__ W2,
             float* __restrict__ C,
             __half* __restrict__ H0, __half* __restrict__ H1, __half* __restrict__ H2,
             int vhalf) {
    extern __shared__ float gsm[];
    float* Asm = gsm;
    float* Bsm = gsm + GNS * GSTG;

    const int z = blockIdx.z;
    const float* A = (z == 0) ? A0 : (z == 1) ? A1 : A2;
    const float* W = (z == 0) ? W0 : (z == 1) ? W1 : W2;
    __half* H = (z == 0) ? H0 : (z == 1) ? H1 : H2;

    const int m0 = blockIdx.y * GBM;
    const int n0 = blockIdx.x * GBN;
    const int tid = threadIdx.x;
    const int w = tid >> 5, lane = tid & 31;
    const int g = lane >> 2, tig = lane & 3;
    const int wm = (w >> 2) * 64;
    const int wn = (w & 3) * 32;

    const int lr = tid >> 3;
    const int lc = (tid & 7) << 2;

    const uint32_t sA = (uint32_t)__cvta_generic_to_shared(Asm);
    const uint32_t sB = (uint32_t)__cvta_generic_to_shared(Bsm);

    const int lane7 = lane & 7;
    const int a_ro = ((lane >> 3) & 1) * 8;
    const int a_ko = ((lane >> 4) & 1) * 4;
    const int b_no = ((lane >> 4) & 1) * 8;
    const int b_ko = ((lane >> 3) & 1) * 4;

    uint32_t aIdx[4];
#pragma unroll
    for (int mt = 0; mt < 4; mt++)
        aIdx[mt] = (uint32_t)(((wm + mt * 16 + a_ro + lane7) * GST + a_ko) * 4);
    const uint32_t bIdx = (uint32_t)(((wn + b_no + lane7) * GST + b_ko) * 4);

    float acc[4][4][4];
#pragma unroll
    for (int i = 0; i < 4; i++)
#pragma unroll
        for (int j = 0; j < 4; j++)
#pragma unroll
            for (int e = 0; e < 4; e++) acc[i][j][e] = 0.f;

    auto issue = [&](int st, int k0) {
#pragma unroll
        for (int it = 0; it < 4; it++) {
            int row = lr + it * 32;
            cp16(sA + (uint32_t)((st * GBM + row) * GST + lc) * 4,
                 &A[(size_t)(m0 + row) * DDIM + k0 + lc]);
            cp16(sB + (uint32_t)((st * GBN + row) * GST + lc) * 4,
                 &W[(size_t)(n0 + row) * DDIM + k0 + lc]);
        }
    };

    issue(0, 0); cp_commit();
    issue(1, GBK); cp_commit();

    const int NKT = DDIM / GBK;
    for (int kt = 0; kt < NKT; kt++) {
        if (kt < NKT - 1) cp_wait<1>(); else cp_wait<0>();
        __syncthreads();

        const int st = kt % GNS;
        const uint32_t stb = (uint32_t)(st * GSTG * 4);

#pragma unroll
        for (int ks = 0; ks < 4; ks++) {
            const uint32_t ksB = (uint32_t)(ks * 32);
            uint32_t b[4][2];
            uint32_t bb = sB + stb + bIdx + ksB;
            ldsm4(b[0][0], b[0][1], b[1][0], b[1][1], bb);
            ldsm4(b[2][0], b[2][1], b[3][0], b[3][1], bb + 16 * GST * 4);
            uint32_t a[4][4];
#pragma unroll
            for (int mt = 0; mt < 4; mt++)
                ldsm4(a[mt][0], a[mt][1], a[mt][2], a[mt][3], sA + stb + aIdx[mt] + ksB);

#pragma unroll
            for (int nt = 0; nt < 4; nt++) {
                b[nt][0] = bits2tf32(b[nt][0]);
                b[nt][1] = bits2tf32(b[nt][1]);
            }
#pragma unroll
            for (int mt = 0; mt < 4; mt++) {
#pragma unroll
                for (int e = 0; e < 4; e++) a[mt][e] = bits2tf32(a[mt][e]);
#pragma unroll
                for (int nt = 0; nt < 4; nt++)
                    mma_tf32(acc[mt][nt], a[mt][0], a[mt][1], a[mt][2], a[mt][3],
                             b[nt][0], b[nt][1]);
            }
        }

        if (kt + 2 < NKT) {
            issue((kt + 2) % GNS, (kt + 2) * GBK);
            cp_commit();
        }
    }

#pragma unroll
    for (int mt = 0; mt < 4; mt++) {
        int r0 = m0 + wm + mt * 16 + g;
#pragma unroll
        for (int nt = 0; nt < 4; nt++) {
            int col = n0 + wn + nt * 8 + 2 * tig;
            float v0 = acc[mt][nt][0], v1 = acc[mt][nt][1];
            float v2 = acc[mt][nt][2], v3 = acc[mt][nt][3];
            if (vhalf) {
                *reinterpret_cast<__half2*>(&H[(size_t)r0 * DDIM + col]) =
                    __floats2half2_rn(v0, v1);
                *reinterpret_cast<__half2*>(&H[(size_t)(r0 + 8) * DDIM + col]) =
                    __floats2half2_rn(v2, v3);
            } else {
                *reinterpret_cast<float2*>(&C[(size_t)r0 * DDIM + col]) = make_float2(v0, v1);
                *reinterpret_cast<float2*>(&C[(size_t)(r0 + 8) * DDIM + col]) = make_float2(v2, v3);
            }
        }
    }
}

// ---------------- flash attention: all-fp16 operands, fp32 accum/softmax ----------------
// 256-row Q tile, 8 warps; Q/K/V fp16 in smem; P register-resident fp16
#define AQT 256
#define ATHR 256
#define HPH 72    // fp16 row stride (halves): 144B rows -> LDSM/trans-LDSM conflict-free
#define ASMEM ((2*64*HPH + 2*64*HPH + AQT*HPH) * 2 + 2 * 64 * 4)   // 74240 B

__global__ __launch_bounds__(ATHR, 1)
void attn_kernel(const __half* __restrict__ QH, const __half* __restrict__ KH,
                 const __half* __restrict__ VH,
                 const int* __restrict__ mask, float* __restrict__ O) {
    extern __shared__ uint32_t smem_u[];
    __half* Kh0 = (__half*)smem_u;                 // 2 stages x 64 rows (keys x dims)
    __half* Vh0 = Kh0 + 2 * 64 * HPH;              // 2 stages x 64 rows
    __half* Qs  = Vh0 + 2 * 64 * HPH;              // AQT rows (Q staging, scaled)
    int* msk0 = (int*)(Qs + AQT * HPH);

    const int qi = gridDim.x - 1 - blockIdx.x;     // heavy tiles first
    const int bh = blockIdx.y;
    const int b = bh / HH, h = bh % HH;

    const int tid = threadIdx.x;
    const int w = tid >> 5, lane = tid & 31;
    const int g = lane >> 2, tig = lane & 3;
    const int wrow = w * 32;

    const __half* Qb = QH + ((size_t)b * SS + (size_t)qi * AQT) * DDIM + h * DKK;
    const __half* Kb = KH + (size_t)b * SS * DDIM + h * DKK;
    const __half* Vb = VH + (size_t)b * SS * DDIM + h * DKK;
    float* Ob = O + ((size_t)b * SS + (size_t)qi * AQT) * DDIM + h * DKK;

    const uint32_t sK = (uint32_t)__cvta_generic_to_shared(Kh0);
    const uint32_t sV = (uint32_t)__cvta_generic_to_shared(Vh0);
    const uint32_t sQ = (uint32_t)__cvta_generic_to_shared(Qs);
    const uint32_t sM = (uint32_t)__cvta_generic_to_shared(msk0);

    const int lane7 = lane & 7;
    // fp16 A-frag (m16n8k16 row-major): rows +a_ro, 16B col offset by (lane>>4)
    const int a_ro = ((lane >> 3) & 1) * 8;
    const int a_kh = ((lane >> 4) & 1) * 8;        // halves
    // fp16 B-frag (col-major = [n][k] storage): rows(n) +b_no, 16B col by (lane>>3)
    const int b_no = ((lane >> 4) & 1) * 8;
    const int b_kh = ((lane >> 3) & 1) * 8;        // halves
    // trans-ldsm for V: row = k (key), col half-offset
    const int v_ro = lane & 15;
    const int v_co = (lane >> 4) * 8;

    const float qscale = 0.125f * 1.4426950408889634f;

    auto issueKV = [&](int st, int kt) {
        const __half* Kt = Kb + (size_t)kt * 64 * DDIM;
        const __half* Vt = Vb + (size_t)kt * 64 * DDIM;
#pragma unroll
        for (int t = 0; t < 2; t++) {              // K: 512 x 16B; V: 512 x 16B
            int i = tid + t * ATHR;
            int r = i >> 3;
            int c8 = (i & 7) << 3;
            uint32_t off = (uint32_t)((st * 64 + r) * HPH + c8) * 2;
            cp16(sK + off, Kt + (size_t)r * DDIM + c8);
            cp16(sV + off, Vt + (size_t)r * DDIM + c8);
        }
        if (tid < 64) cp4(sM + (uint32_t)(st * 64 + tid) * 4, &mask[(size_t)b * SS + kt * 64 + tid]);
    };

    const int ktmax = (AQT / 64) * qi + (AQT / 64) - 1;   // 4*qi + 3
    issueKV(0, 0);
    cp_commit();

    // stage Q (AQT x 64 halves), scaled by qscale
#pragma unroll
    for (int t = 0; t < 8; t++) {
        int i = tid + t * ATHR;
        int r = i >> 3;
        int c8 = (i & 7) << 3;
        uint4 raw = *reinterpret_cast<const uint4*>(Qb + (size_t)r * DDIM + c8);
        const __half2* hp = reinterpret_cast<const __half2*>(&raw);
        uint4 outp;
        uint32_t* op = reinterpret_cast<uint32_t*>(&outp);
#pragma unroll
        for (int e = 0; e < 4; e++) {
            float2 f = __half22float2(hp[e]);
            op[e] = packh2(f.x * qscale, f.y * qscale);
        }
        *reinterpret_cast<uint4*>(&Qs[r * HPH + c8]) = outp;
    }
    __syncthreads();

    // Q fragments: fp16 A-frags, 4 k16-steps
    uint32_t qf[2][4][4];
#pragma unroll
    for (int mt = 0; mt < 2; mt++) {
        const uint32_t base = sQ + (uint32_t)(((wrow + mt * 16 + a_ro + lane7) * HPH + a_kh) * 2);
#pragma unroll
        for (int ks = 0; ks < 4; ks++)
            ldsm4(qf[mt][ks][0], qf[mt][ks][1], qf[mt][ks][2], qf[mt][ks][3],
                  base + (uint32_t)(ks * 32));
    }

    float mrow[2][2], lrow[2][2];
    float o[2][8][4];
#pragma unroll
    for (int mt = 0; mt < 2; mt++) {
        mrow[mt][0] = mrow[mt][1] = -1e30f;
        lrow[mt][0] = lrow[mt][1] = 0.f;
#pragma unroll
        for (int nt = 0; nt < 8; nt++)
#pragma unroll
            for (int e = 0; e < 4; e++) o[mt][nt][e] = 0.f;
    }

    const int rowmax = qi * AQT + wrow + 31;

    for (int kt = 0; kt <= ktmax; kt++) {
        const int cur = kt & 1;
        __syncthreads();
        if (kt < ktmax) {
            issueKV(cur ^ 1, kt + 1);
            cp_commit();
            cp_wait<1>();
        } else {
            cp_wait<0>();
        }
        __syncthreads();

        const uint32_t sKst = sK + (uint32_t)(cur * 64 * HPH * 2);
        const uint32_t vH0 = sV + (uint32_t)(cur * 64 * HPH * 2)
                           + (uint32_t)(v_ro * HPH + v_co) * 2;
        const int* msk = msk0 + cur * 64;

        if (kt * 64 > rowmax) continue;

        const int mvl0 = msk[lane], mvl1 = msk[32 + lane];
        const bool allvalid = __all_sync(0xffffffffu, (mvl0 != 0) && (mvl1 != 0));

        // S = Q @ K^T : 32x64 per warp, fp16 k16
        float s[2][8][4];
#pragma unroll
        for (int mt = 0; mt < 2; mt++)
#pragma unroll
            for (int nt = 0; nt < 8; nt++)
                s[mt][nt][0] = s[mt][nt][1] = s[mt][nt][2] = s[mt][nt][3] = 0.f;

        const uint32_t kb0 = sKst + (uint32_t)(((b_no + lane7) * HPH + b_kh) * 2);
#pragma unroll
        for (int ks = 0; ks < 4; ks++) {
            const uint32_t ksB = (uint32_t)(ks * 32);   // 16 halves
            uint32_t bf[8][2];
#pragma unroll
            for (int j = 0; j < 4; j++)                 // key groups of 16
                ldsm4(bf[2*j][0], bf[2*j][1], bf[2*j+1][0], bf[2*j+1][1],
                      kb0 + (uint32_t)(j * 16 * HPH * 2) + ksB);
#pragma unroll
            for (int mt = 0; mt < 2; mt++)
#pragma unroll
                for (int nt = 0; nt < 8; nt++)
                    mma_f16(s[mt][nt], qf[mt][ks][0], qf[mt][ks][1],
                            qf[mt][ks][2], qf[mt][ks][3], bf[nt][0], bf[nt][1]);
        }

        // masking + online softmax; P packed to fp16 registers
        uint32_t ph[2][8][2];
#pragma unroll
        for (int mt = 0; mt < 2; mt++) {
            const int q0 = qi * AQT + wrow + mt * 16 + g;
            const int q1 = q0 + 8;
            const bool needc = (kt * 64 + 63 > qi * AQT + wrow + mt * 16);

            if (!allvalid) {
#pragma unroll
                for (int nt = 0; nt < 8; nt++) {
                    int cl = nt * 8 + 2 * tig;
                    int cg = kt * 64 + cl;
                    bool mv0 = (msk[cl] != 0);
                    bool mv1 = (msk[cl + 1] != 0);
                    if (!mv0 || (needc && cg > q0))     s[mt][nt][0] = -1e30f;
                    if (!mv1 || (needc && cg + 1 > q0)) s[mt][nt][1] = -1e30f;
                    if (!mv0 || (needc && cg > q1))     s[mt][nt][2] = -1e30f;
                    if (!mv1 || (needc && cg + 1 > q1)) s[mt][nt][3] = -1e30f;
                }
            } else if (needc) {
#pragma unroll
                for (int nt = 0; nt < 8; nt++) {
                    int cg = kt * 64 + nt * 8 + 2 * tig;
                    if (cg > q0)     s[mt][nt][0] = -1e30f;
                    if (cg + 1 > q0) s[mt][nt][1] = -1e30f;
                    if (cg > q1)     s[mt][nt][2] = -1e30f;
                    if (cg + 1 > q1) s[mt][nt][3] = -1e30f;
                }
            }

            float rm0 = -1e30f, rm1 = -1e30f;
#pragma unroll
            for (int nt = 0; nt < 8; nt++) {
                rm0 = fmaxf(rm0, fmaxf(s[mt][nt][0], s[mt][nt][1]));
                rm1 = fmaxf(rm1, fmaxf(s[mt][nt][2], s[mt][nt][3]));
            }
            rm0 = fmaxf(rm0, __shfl_xor_sync(0xffffffffu, rm0, 1));
            rm0 = fmaxf(rm0, __shfl_xor_sync(0xffffffffu, rm0, 2));
            rm1 = fmaxf(rm1, __shfl_xor_sync(0xffffffffu, rm1, 1));
            rm1 = fmaxf(rm1, __shfl_xor_sync(0xffffffffu, rm1, 2));

            float mn0 = fmaxf(mrow[mt][0], rm0);
            float mn1 = fmaxf(mrow[mt][1], rm1);
            float al0 = ex2(mrow[mt][0] - mn0);
            float al1 = ex2(mrow[mt][1] - mn1);
            mrow[mt][0] = mn0; mrow[mt][1] = mn1;

            float rs0 = 0.f, rs1 = 0.f;
#pragma unroll
            for (int nt = 0; nt < 8; nt++) {
                float p0 = ex2(s[mt][nt][0] - mn0);
                float p1 = ex2(s[mt][nt][1] - mn0);
                float p2 = ex2(s[mt][nt][2] - mn1);
                float p3 = ex2(s[mt][nt][3] - mn1);
                rs0 += p0 + p1;
                rs1 += p2 + p3;
                ph[mt][nt][0] = packh2(p0, p1);   // row g
                ph[mt][nt][1] = packh2(p2, p3);   // row g+8
            }
            rs0 += __shfl_xor_sync(0xffffffffu, rs0, 1);
            rs0 += __shfl_xor_sync(0xffffffffu, rs0, 2);
            rs1 += __shfl_xor_sync(0xffffffffu, rs1, 1);
            rs1 += __shfl_xor_sync(0xffffffffu, rs1, 2);
            lrow[mt][0] = lrow[mt][0] * al0 + rs0;
            lrow[mt][1] = lrow[mt][1] * al1 + rs1;

#pragma unroll
            for (int nt = 0; nt < 8; nt++) {
                o[mt][nt][0] *= al0; o[mt][nt][1] *= al0;
                o[mt][nt][2] *= al1; o[mt][nt][3] *= al1;
            }
        }

        // O += P @ V, fp16 m16n8k16, P in registers, V via ldmatrix.trans
#pragma unroll
        for (int j = 0; j < 4; j++) {              // k-steps of 16 keys
            const uint32_t jb = (uint32_t)(j * 16 * HPH * 2);
            uint32_t vf[8][2];
#pragma unroll
            for (int dgi = 0; dgi < 4; dgi++)
                ldsm4t(vf[2*dgi][0], vf[2*dgi][1], vf[2*dgi+1][0], vf[2*dgi+1][1],
                       vH0 + jb + (uint32_t)(dgi * 32));
#pragma unroll
            for (int mt = 0; mt < 2; mt++) {
                uint32_t a0 = ph[mt][2*j][0],   a1 = ph[mt][2*j][1];
                uint32_t a2 = ph[mt][2*j+1][0], a3 = ph[mt][2*j+1][1];
#pragma unroll
                for (int nt = 0; nt < 8; nt++)
                    mma_f16(o[mt][nt], a0, a1, a2, a3, vf[nt][0], vf[nt][1]);
            }
        }
    }

    // normalize + store (rounded: feeds the Wo tf32 GEMM)
#pragma unroll
    for (int mt = 0; mt < 2; mt++) {
        float i0 = 1.f / lrow[mt][0];
        float i1 = 1.f / lrow[mt][1];
        int r0 = wrow + mt * 16 + g;
#pragma unroll
        for (int nt = 0; nt < 8; nt++) {
            int cl = nt * 8 + 2 * tig;
            *reinterpret_cast<float2*>(&Ob[(size_t)r0 * DDIM + cl]) =
                make_float2(__uint_as_float(f2tf32(o[mt][nt][0] * i0)),
                            __uint_as_float(f2tf32(o[mt][nt][1] * i0)));
            *reinterpret_cast<float2*>(&Ob[(size_t)(r0 + 8) * DDIM + cl]) =
                make_float2(__uint_as_float(f2tf32(o[mt][nt][2] * i1)),
                            __uint_as_float(f2tf32(o[mt][nt][3] * i1)));
        }
    }
}

// ---------------- launch ----------------
extern "C" void kernel_launch(void* const* d_in, const int* in_sizes, int n_in,
                              void* d_out, int out_size) {
    const float* xq = (const float*)d_in[0];
    const float* xk = (const float*)d_in[1];
    const float* xv = (const float*)d_in[2];
    const int* mask = (const int*)d_in[3];
    const float* Wq = (const float*)d_in[4];
    const float* Wk = (const float*)d_in[5];
    const float* Wv = (const float*)d_in[6];
    const float* Wo = (const float*)d_in[7];
    float* out = (float*)d_out;

    float *Ap;
    __half *QHp, *KHp, *VHp;
    cudaGetSymbolAddress((void**)&Ap, g_A);
    cudaGetSymbolAddress((void**)&QHp, g_Qh);
    cudaGetSymbolAddress((void**)&KHp, g_Kh);
    cudaGetSymbolAddress((void**)&VHp, g_Vh);

    cudaFuncSetAttribute(gemm_nt, cudaFuncAttributeMaxDynamicSharedMemorySize, GSMEM);
    cudaFuncSetAttribute(attn_kernel, cudaFuncAttributeMaxDynamicSharedMemorySize, ASMEM);

    // fused QKV projections; Q/K/V written as fp16
    gemm_nt<<<dim3(DDIM / GBN, MTOT / GBM, 3), 256, GSMEM>>>(
        xq, xk, xv, Wq, Wk, Wv, nullptr, QHp, KHp, VHp, 1);

    attn_kernel<<<dim3(SS / AQT, BB * HH), ATHR, ASMEM>>>(QHp, KHp, VHp, mask, Ap);

    // output projection; exact fp32 output (A rounded to tf32 by attn epilogue)
    gemm_nt<<<dim3(DDIM / GBN, MTOT / GBM, 1), 256, GSMEM>>>(
        Ap, Ap, Ap, Wo, Wo, Wo, out, QHp, KHp, VHp, 0);
}

// round 13
// speedup vs baseline: 1.8440x; 1.4998x over previous
#include <cuda_runtime.h>
#include <cuda_fp16.h>
#include <cstdint>

#define BB 4
#define SS 2048
#define DDIM 1024
#define HH 16
#define DKK 64
#define MTOT (BB*SS)   // 8192

// ---------------- scratch (static __device__, allocation-free) ----------------
__device__ __half g_xqh[(size_t)MTOT*DDIM];
__device__ __half g_xkh[(size_t)MTOT*DDIM];
__device__ __half g_xvh[(size_t)MTOT*DDIM];
__device__ __half g_Wh[4][(size_t)DDIM*DDIM];
__device__ __half g_Qh[(size_t)MTOT*DDIM];
__device__ __half g_Kh[(size_t)MTOT*DDIM];
__device__ __half g_Vh[(size_t)MTOT*DDIM];
__device__ __half g_Ah[(size_t)MTOT*DDIM];

// ---------------- helpers ----------------
__device__ __forceinline__ float ex2(float x) {
    float y;
    asm("ex2.approx.ftz.f32 %0, %1;" : "=f"(y) : "f"(x));
    return y;
}
__device__ __forceinline__ uint32_t packh2(float lo, float hi) {
    __half2 h = __floats2half2_rn(lo, hi);
    return *reinterpret_cast<uint32_t*>(&h);
}
__device__ __forceinline__ void cp16(uint32_t saddr, const void* g) {
    asm volatile("cp.async.cg.shared.global [%0], [%1], 16;" :: "r"(saddr), "l"(g));
}
__device__ __forceinline__ void cp4(uint32_t saddr, const void* g) {
    asm volatile("cp.async.ca.shared.global [%0], [%1], 4;" :: "r"(saddr), "l"(g));
}
__device__ __forceinline__ void cp_commit() {
    asm volatile("cp.async.commit_group;");
}
template <int N>
__device__ __forceinline__ void cp_wait() {
    asm volatile("cp.async.wait_group %0;" :: "n"(N));
}
__device__ __forceinline__ void ldsm4(uint32_t& r0, uint32_t& r1, uint32_t& r2, uint32_t& r3,
                                      uint32_t addr) {
    asm volatile("ldmatrix.sync.aligned.m8n8.x4.shared.b16 {%0,%1,%2,%3}, [%4];"
                 : "=r"(r0), "=r"(r1), "=r"(r2), "=r"(r3) : "r"(addr));
}
__device__ __forceinline__ void ldsm4t(uint32_t& r0, uint32_t& r1, uint32_t& r2, uint32_t& r3,
                                       uint32_t addr) {
    asm volatile("ldmatrix.sync.aligned.m8n8.x4.trans.shared.b16 {%0,%1,%2,%3}, [%4];"
                 : "=r"(r0), "=r"(r1), "=r"(r2), "=r"(r3) : "r"(addr));
}
// D(16x8,f32) += A(16x16,f16,row) * B(16x8,f16,col)
__device__ __forceinline__ void mma_f16(float c[4],
                                        uint32_t a0, uint32_t a1, uint32_t a2, uint32_t a3,
                                        uint32_t b0, uint32_t b1) {
    asm volatile(
        "mma.sync.aligned.m16n8k16.row.col.f32.f16.f16.f32 "
        "{%0,%1,%2,%3}, {%4,%5,%6,%7}, {%8,%9}, {%0,%1,%2,%3};"
        : "+f"(c[0]), "+f"(c[1]), "+f"(c[2]), "+f"(c[3])
        : "r"(a0), "r"(a1), "r"(a2), "r"(a3), "r"(b0), "r"(b1));
}

// ---------------- fp32 -> fp16 conversion (one-time) ----------------
__global__ void f32to16_k(const float4* __restrict__ in, uint4* __restrict__ out, int n8) {
    int i = blockIdx.x * blockDim.x + threadIdx.x;
    int stride = gridDim.x * blockDim.x;
    for (; i < n8; i += stride) {
        float4 v0 = in[2 * i];
        float4 v1 = in[2 * i + 1];
        uint4 o;
        o.x = packh2(v0.x, v0.y);
        o.y = packh2(v0.z, v0.w);
        o.z = packh2(v1.x, v1.y);
        o.w = packh2(v1.z, v1.w);
        out[i] = o;
    }
}

// ---------------- fp16 GEMM: C[m][n] = sum_k A[m][k] * W[n][k] ----------------
// tile 128x128xk64, warp 64x32, 3-stage cp.async, ldmatrix fp16 fragments
#define GBM 128
#define GBN 128
#define GBKH 64                               // k per tile (halves)
#define GSTH 72                               // row stride in halves (144B rows)
#define GSTGH (GBM * GSTH)                    // halves per stage per matrix
#define GNS 3
#define GSMEM (2 * GNS * GSTGH * 2)           // 110592 B

__global__ __launch_bounds__(256, 2)
void gemm_h(const __half* __restrict__ A0, const __half* __restrict__ A1, const __half* __restrict__ A2,
            const __half* __restrict__ W0, const __half* __restrict__ W1, const __half* __restrict__ W2,
            float* __restrict__ C,
            __half* __restrict__ H0, __half* __restrict__ H1, __half* __restrict__ H2,
            int outHalf) {
    extern __shared__ __half hsm[];
    __half* Asm = hsm;
    __half* Bsm = hsm + GNS * GSTGH;

    const int z = blockIdx.z;
    const __half* A = (z == 0) ? A0 : (z == 1) ? A1 : A2;
    const __half* W = (z == 0) ? W0 : (z == 1) ? W1 : W2;
    __half* H = (z == 0) ? H0 : (z == 1) ? H1 : H2;

    const int m0 = blockIdx.y * GBM;
    const int n0 = blockIdx.x * GBN;
    const int tid = threadIdx.x;
    const int w = tid >> 5, lane = tid & 31;
    const int g = lane >> 2, tig = lane & 3;
    const int wm = (w >> 2) * 64;   // 2 warp rows
    const int wn = (w & 3) * 32;    // 4 warp cols

    const uint32_t sA = (uint32_t)__cvta_generic_to_shared(Asm);
    const uint32_t sB = (uint32_t)__cvta_generic_to_shared(Bsm);

    const int lane7 = lane & 7;
    // fp16 A-frag: rows +8 by (lane>>3)&1, k +8 halves by (lane>>4)&1
    const int a_ro = ((lane >> 3) & 1) * 8;
    const int a_kh = ((lane >> 4) & 1) * 8;
    // fp16 B-frag ([n][k] storage): n +8 by (lane>>4)&1, k +8 halves by (lane>>3)&1
    const int b_no = ((lane >> 4) & 1) * 8;
    const int b_kh = ((lane >> 3) & 1) * 8;

    uint32_t aIdx[4];
#pragma unroll
    for (int mt = 0; mt < 4; mt++)
        aIdx[mt] = (uint32_t)(((wm + mt * 16 + a_ro + lane7) * GSTH + a_kh) * 2);
    uint32_t bIdx[2];
#pragma unroll
    for (int nb = 0; nb < 2; nb++)
        bIdx[nb] = (uint32_t)(((wn + nb * 16 + b_no + lane7) * GSTH + b_kh) * 2);

    float acc[4][4][4];
#pragma unroll
    for (int i = 0; i < 4; i++)
#pragma unroll
        for (int j = 0; j < 4; j++)
#pragma unroll
            for (int e = 0; e < 4; e++) acc[i][j][e] = 0.f;

    const int lr = tid >> 3;          // 0..31
    const int lc8 = (tid & 7) << 3;   // half offset 0..56

    auto issue = [&](int st, int k0) {
#pragma unroll
        for (int it = 0; it < 4; it++) {
            int row = lr + it * 32;
            cp16(sA + (uint32_t)((st * GBM + row) * GSTH + lc8) * 2,
                 &A[(size_t)(m0 + row) * DDIM + k0 + lc8]);
            cp16(sB + (uint32_t)((st * GBN + row) * GSTH + lc8) * 2,
                 &W[(size_t)(n0 + row) * DDIM + k0 + lc8]);
        }
    };

    issue(0, 0); cp_commit();
    issue(1, GBKH); cp_commit();

    const int NKT = DDIM / GBKH;      // 16
    for (int kt = 0; kt < NKT; kt++) {
        if (kt < NKT - 1) cp_wait<1>(); else cp_wait<0>();
        __syncthreads();

        const int st = kt % GNS;
        const uint32_t stb = (uint32_t)(st * GSTGH * 2);

#pragma unroll
        for (int ks = 0; ks < 4; ks++) {
            const uint32_t ksB = (uint32_t)(ks * 32);   // 16 halves
            uint32_t b[4][2];
            ldsm4(b[0][0], b[0][1], b[1][0], b[1][1], sB + stb + bIdx[0] + ksB);
            ldsm4(b[2][0], b[2][1], b[3][0], b[3][1], sB + stb + bIdx[1] + ksB);
#pragma unroll
            for (int mt = 0; mt < 4; mt++) {
                uint32_t a0, a1, a2, a3;
                ldsm4(a0, a1, a2, a3, sA + stb + aIdx[mt] + ksB);
#pragma unroll
                for (int nt = 0; nt < 4; nt++)
                    mma_f16(acc[mt][nt], a0, a1, a2, a3, b[nt][0], b[nt][1]);
            }
        }

        if (kt + 2 < NKT) {
            issue((kt + 2) % GNS, (kt + 2) * GBKH);
            cp_commit();
        }
    }

#pragma unroll
    for (int mt = 0; mt < 4; mt++) {
        int r0 = m0 + wm + mt * 16 + g;
#pragma unroll
        for (int nt = 0; nt < 4; nt++) {
            int col = n0 + wn + nt * 8 + 2 * tig;
            float v0 = acc[mt][nt][0], v1 = acc[mt][nt][1];
            float v2 = acc[mt][nt][2], v3 = acc[mt][nt][3];
            if (outHalf) {
                *reinterpret_cast<__half2*>(&H[(size_t)r0 * DDIM + col]) =
                    __floats2half2_rn(v0, v1);
                *reinterpret_cast<__half2*>(&H[(size_t)(r0 + 8) * DDIM + col]) =
                    __floats2half2_rn(v2, v3);
            } else {
                *reinterpret_cast<float2*>(&C[(size_t)r0 * DDIM + col]) = make_float2(v0, v1);
                *reinterpret_cast<float2*>(&C[(size_t)(r0 + 8) * DDIM + col]) = make_float2(v2, v3);
            }
        }
    }
}

// ---------------- flash attention: all-fp16 operands, fp32 accum/softmax (R12 proven) ----------------
#define AQT 256
#define ATHR 256
#define HPH 72    // fp16 row stride (halves)
#define ASMEM ((2*64*HPH + 2*64*HPH + AQT*HPH) * 2 + 2 * 64 * 4)   // 74240 B

__global__ __launch_bounds__(ATHR, 1)
void attn_kernel(const __half* __restrict__ QH, const __half* __restrict__ KH,
                 const __half* __restrict__ VH,
                 const int* __restrict__ mask, __half* __restrict__ O) {
    extern __shared__ uint32_t smem_u[];
    __half* Kh0 = (__half*)smem_u;                 // 2 stages x 64 rows (keys x dims)
    __half* Vh0 = Kh0 + 2 * 64 * HPH;              // 2 stages x 64 rows
    __half* Qs  = Vh0 + 2 * 64 * HPH;              // AQT rows (Q staging, scaled)
    int* msk0 = (int*)(Qs + AQT * HPH);

    const int qi = gridDim.x - 1 - blockIdx.x;     // heavy tiles first
    const int bh = blockIdx.y;
    const int b = bh / HH, h = bh % HH;

    const int tid = threadIdx.x;
    const int w = tid >> 5, lane = tid & 31;
    const int g = lane >> 2, tig = lane & 3;
    const int wrow = w * 32;

    const __half* Qb = QH + ((size_t)b * SS + (size_t)qi * AQT) * DDIM + h * DKK;
    const __half* Kb = KH + (size_t)b * SS * DDIM + h * DKK;
    const __half* Vb = VH + (size_t)b * SS * DDIM + h * DKK;
    __half* Ob = O + ((size_t)b * SS + (size_t)qi * AQT) * DDIM + h * DKK;

    const uint32_t sK = (uint32_t)__cvta_generic_to_shared(Kh0);
    const uint32_t sV = (uint32_t)__cvta_generic_to_shared(Vh0);
    const uint32_t sQ = (uint32_t)__cvta_generic_to_shared(Qs);
    const uint32_t sM = (uint32_t)__cvta_generic_to_shared(msk0);

    const int lane7 = lane & 7;
    const int a_ro = ((lane >> 3) & 1) * 8;
    const int a_kh = ((lane >> 4) & 1) * 8;
    const int b_no = ((lane >> 4) & 1) * 8;
    const int b_kh = ((lane >> 3) & 1) * 8;
    const int v_ro = lane & 15;
    const int v_co = (lane >> 4) * 8;

    const float qscale = 0.125f * 1.4426950408889634f;

    auto issueKV = [&](int st, int kt) {
        const __half* Kt = Kb + (size_t)kt * 64 * DDIM;
        const __half* Vt = Vb + (size_t)kt * 64 * DDIM;
#pragma unroll
        for (int t = 0; t < 2; t++) {
            int i = tid + t * ATHR;
            int r = i >> 3;
            int c8 = (i & 7) << 3;
            uint32_t off = (uint32_t)((st * 64 + r) * HPH + c8) * 2;
            cp16(sK + off, Kt + (size_t)r * DDIM + c8);
            cp16(sV + off, Vt + (size_t)r * DDIM + c8);
        }
        if (tid < 64) cp4(sM + (uint32_t)(st * 64 + tid) * 4, &mask[(size_t)b * SS + kt * 64 + tid]);
    };

    const int ktmax = (AQT / 64) * qi + (AQT / 64) - 1;   // 4*qi + 3
    issueKV(0, 0);
    cp_commit();

    // stage Q (AQT x 64 halves), scaled by qscale
#pragma unroll
    for (int t = 0; t < 8; t++) {
        int i = tid + t * ATHR;
        int r = i >> 3;
        int c8 = (i & 7) << 3;
        uint4 raw = *reinterpret_cast<const uint4*>(Qb + (size_t)r * DDIM + c8);
        const __half2* hp = reinterpret_cast<const __half2*>(&raw);
        uint4 outp;
        uint32_t* op = reinterpret_cast<uint32_t*>(&outp);
#pragma unroll
        for (int e = 0; e < 4; e++) {
            float2 f = __half22float2(hp[e]);
            op[e] = packh2(f.x * qscale, f.y * qscale);
        }
        *reinterpret_cast<uint4*>(&Qs[r * HPH + c8]) = outp;
    }
    __syncthreads();

    uint32_t qf[2][4][4];
#pragma unroll
    for (int mt = 0; mt < 2; mt++) {
        const uint32_t base = sQ + (uint32_t)(((wrow + mt * 16 + a_ro + lane7) * HPH + a_kh) * 2);
#pragma unroll
        for (int ks = 0; ks < 4; ks++)
            ldsm4(qf[mt][ks][0], qf[mt][ks][1], qf[mt][ks][2], qf[mt][ks][3],
                  base + (uint32_t)(ks * 32));
    }

    float mrow[2][2], lrow[2][2];
    float o[2][8][4];
#pragma unroll
    for (int mt = 0; mt < 2; mt++) {
        mrow[mt][0] = mrow[mt][1] = -1e30f;
        lrow[mt][0] = lrow[mt][1] = 0.f;
#pragma unroll
        for (int nt = 0; nt < 8; nt++)
#pragma unroll
            for (int e = 0; e < 4; e++) o[mt][nt][e] = 0.f;
    }

    const int rowmax = qi * AQT + wrow + 31;

    for (int kt = 0; kt <= ktmax; kt++) {
        const int cur = kt & 1;
        __syncthreads();
        if (kt < ktmax) {
            issueKV(cur ^ 1, kt + 1);
            cp_commit();
            cp_wait<1>();
        } else {
            cp_wait<0>();
        }
        __syncthreads();

        const uint32_t sKst = sK + (uint32_t)(cur * 64 * HPH * 2);
        const uint32_t vH0 = sV + (uint32_t)(cur * 64 * HPH * 2)
                           + (uint32_t)(v_ro * HPH + v_co) * 2;
        const int* msk = msk0 + cur * 64;

        if (kt * 64 > rowmax) continue;

        const int mvl0 = msk[lane], mvl1 = msk[32 + lane];
        const bool allvalid = __all_sync(0xffffffffu, (mvl0 != 0) && (mvl1 != 0));

        // S = Q @ K^T : 32x64 per warp, fp16 k16
        float s[2][8][4];
#pragma unroll
        for (int mt = 0; mt < 2; mt++)
#pragma unroll
            for (int nt = 0; nt < 8; nt++)
                s[mt][nt][0] = s[mt][nt][1] = s[mt][nt][2] = s[mt][nt][3] = 0.f;

        const uint32_t kb0 = sKst + (uint32_t)(((b_no + lane7) * HPH + b_kh) * 2);
#pragma unroll
        for (int ks = 0; ks < 4; ks++) {
            const uint32_t ksB = (uint32_t)(ks * 32);
            uint32_t bf[8][2];
#pragma unroll
            for (int j = 0; j < 4; j++)
                ldsm4(bf[2*j][0], bf[2*j][1], bf[2*j+1][0], bf[2*j+1][1],
                      kb0 + (uint32_t)(j * 16 * HPH * 2) + ksB);
#pragma unroll
            for (int mt = 0; mt < 2; mt++)
#pragma unroll
                for (int nt = 0; nt < 8; nt++)
                    mma_f16(s[mt][nt], qf[mt][ks][0], qf[mt][ks][1],
                            qf[mt][ks][2], qf[mt][ks][3], bf[nt][0], bf[nt][1]);
        }

        // masking + online softmax; P packed to fp16 registers
        uint32_t ph[2][8][2];
#pragma unroll
        for (int mt = 0; mt < 2; mt++) {
            const int q0 = qi * AQT + wrow + mt * 16 + g;
            const int q1 = q0 + 8;
            const bool needc = (kt * 64 + 63 > qi * AQT + wrow + mt * 16);

            if (!allvalid) {
#pragma unroll
                for (int nt = 0; nt < 8; nt++) {
                    int cl = nt * 8 + 2 * tig;
                    int cg = kt * 64 + cl;
                    bool mv0 = (msk[cl] != 0);
                    bool mv1 = (msk[cl + 1] != 0);
                    if (!mv0 || (needc && cg > q0))     s[mt][nt][0] = -1e30f;
                    if (!mv1 || (needc && cg + 1 > q0)) s[mt][nt][1] = -1e30f;
                    if (!mv0 || (needc && cg > q1))     s[mt][nt][2] = -1e30f;
                    if (!mv1 || (needc && cg + 1 > q1)) s[mt][nt][3] = -1e30f;
                }
            } else if (needc) {
#pragma unroll
                for (int nt = 0; nt < 8; nt++) {
                    int cg = kt * 64 + nt * 8 + 2 * tig;
                    if (cg > q0)     s[mt][nt][0] = -1e30f;
                    if (cg + 1 > q0) s[mt][nt][1] = -1e30f;
                    if (cg > q1)     s[mt][nt][2] = -1e30f;
                    if (cg + 1 > q1) s[mt][nt][3] = -1e30f;
                }
            }

            float rm0 = -1e30f, rm1 = -1e30f;
#pragma unroll
            for (int nt = 0; nt < 8; nt++) {
                rm0 = fmaxf(rm0, fmaxf(s[mt][nt][0], s[mt][nt][1]));
                rm1 = fmaxf(rm1, fmaxf(s[mt][nt][2], s[mt][nt][3]));
            }
            rm0 = fmaxf(rm0, __shfl_xor_sync(0xffffffffu, rm0, 1));
            rm0 = fmaxf(rm0, __shfl_xor_sync(0xffffffffu, rm0, 2));
            rm1 = fmaxf(rm1, __shfl_xor_sync(0xffffffffu, rm1, 1));
            rm1 = fmaxf(rm1, __shfl_xor_sync(0xffffffffu, rm1, 2));

            float mn0 = fmaxf(mrow[mt][0], rm0);
            float mn1 = fmaxf(mrow[mt][1], rm1);
            float al0 = ex2(mrow[mt][0] - mn0);
            float al1 = ex2(mrow[mt][1] - mn1);
            mrow[mt][0] = mn0; mrow[mt][1] = mn1;

            float rs0 = 0.f, rs1 = 0.f;
#pragma unroll
            for (int nt = 0; nt < 8; nt++) {
                float p0 = ex2(s[mt][nt][0] - mn0);
                float p1 = ex2(s[mt][nt][1] - mn0);
                float p2 = ex2(s[mt][nt][2] - mn1);
                float p3 = ex2(s[mt][nt][3] - mn1);
                rs0 += p0 + p1;
                rs1 += p2 + p3;
                ph[mt][nt][0] = packh2(p0, p1);
                ph[mt][nt][1] = packh2(p2, p3);
            }
            rs0 += __shfl_xor_sync(0xffffffffu, rs0, 1);
            rs0 += __shfl_xor_sync(0xffffffffu, rs0, 2);
            rs1 += __shfl_xor_sync(0xffffffffu, rs1, 1);
            rs1 += __shfl_xor_sync(0xffffffffu, rs1, 2);
            lrow[mt][0] = lrow[mt][0] * al0 + rs0;
            lrow[mt][1] = lrow[mt][1] * al1 + rs1;

#pragma unroll
            for (int nt = 0; nt < 8; nt++) {
                o[mt][nt][0] *= al0; o[mt][nt][1] *= al0;
                o[mt][nt][2] *= al1; o[mt][nt][3] *= al1;
            }
        }

        // O += P @ V, fp16 m16n8k16, P in registers, V via ldmatrix.trans
#pragma unroll
        for (int j = 0; j < 4; j++) {
            const uint32_t jb = (uint32_t)(j * 16 * HPH * 2);
            uint32_t vf[8][2];
#pragma unroll
            for (int dgi = 0; dgi < 4; dgi++)
                ldsm4t(vf[2*dgi][0], vf[2*dgi][1], vf[2*dgi+1][0], vf[2*dgi+1][1],
                       vH0 + jb + (uint32_t)(dgi * 32));
#pragma unroll
            for (int mt = 0; mt < 2; mt++) {
                uint32_t a0 = ph[mt][2*j][0],   a1 = ph[mt][2*j][1];
                uint32_t a2 = ph[mt][2*j+1][0], a3 = ph[mt][2*j+1][1];
#pragma unroll
                for (int nt = 0; nt < 8; nt++)
                    mma_f16(o[mt][nt], a0, a1, a2, a3, vf[nt][0], vf[nt][1]);
            }
        }
    }

    // normalize + store as fp16 (feeds the fp16 Wo GEMM)
#pragma unroll
    for (int mt = 0; mt < 2; mt++) {
        float i0 = 1.f / lrow[mt][0];
        float i1 = 1.f / lrow[mt][1];
        int r0 = wrow + mt * 16 + g;
#pragma unroll
        for (int nt = 0; nt < 8; nt++) {
            int cl = nt * 8 + 2 * tig;
            *reinterpret_cast<__half2*>(&Ob[(size_t)r0 * DDIM + cl]) =
                __floats2half2_rn(o[mt][nt][0] * i0, o[mt][nt][1] * i0);
            *reinterpret_cast<__half2*>(&Ob[(size_t)(r0 + 8) * DDIM + cl]) =
                __floats2half2_rn(o[mt][nt][2] * i1, o[mt][nt][3] * i1);
        }
    }
}

// ---------------- launch ----------------
extern "C" void kernel_launch(void* const* d_in, const int* in_sizes, int n_in,
                              void* d_out, int out_size) {
    const float* xq = (const float*)d_in[0];
    const float* xk = (const float*)d_in[1];
    const float* xv = (const float*)d_in[2];
    const int* mask = (const int*)d_in[3];
    const float* Wq = (const float*)d_in[4];
    const float* Wk = (const float*)d_in[5];
    const float* Wv = (const float*)d_in[6];
    const float* Wo = (const float*)d_in[7];
    float* out = (float*)d_out;

    __half *xqh, *xkh, *xvh, *Wh, *QHp, *KHp, *VHp, *AHp;
    cudaGetSymbolAddress((void**)&xqh, g_xqh);
    cudaGetSymbolAddress((void**)&xkh, g_xkh);
    cudaGetSymbolAddress((void**)&xvh, g_xvh);
    cudaGetSymbolAddress((void**)&Wh, g_Wh);
    cudaGetSymbolAddress((void**)&QHp, g_Qh);
    cudaGetSymbolAddress((void**)&KHp, g_Kh);
    cudaGetSymbolAddress((void**)&VHp, g_Vh);
    cudaGetSymbolAddress((void**)&AHp, g_Ah);

    __half* Wqh = Wh;
    __half* Wkh = Wh + (size_t)DDIM * DDIM;
    __half* Wvh = Wh + 2 * (size_t)DDIM * DDIM;
    __half* Woh = Wh + 3 * (size_t)DDIM * DDIM;

    cudaFuncSetAttribute(gemm_h, cudaFuncAttributeMaxDynamicSharedMemorySize, GSMEM);
    cudaFuncSetAttribute(attn_kernel, cudaFuncAttributeMaxDynamicSharedMemorySize, ASMEM);

    const int NX8 = (MTOT * DDIM) / 8;   // 1048576
    const int NW8 = (DDIM * DDIM) / 8;   // 131072
    f32to16_k<<<2048, 256>>>((const float4*)xq, (uint4*)xqh, NX8);
    f32to16_k<<<2048, 256>>>((const float4*)xk, (uint4*)xkh, NX8);
    f32to16_k<<<2048, 256>>>((const float4*)xv, (uint4*)xvh, NX8);
    f32to16_k<<<512, 256>>>((const float4*)Wq, (uint4*)Wqh, NW8);
    f32to16_k<<<512, 256>>>((const float4*)Wk, (uint4*)Wkh, NW8);
    f32to16_k<<<512, 256>>>((const float4*)Wv, (uint4*)Wvh, NW8);
    f32to16_k<<<512, 256>>>((const float4*)Wo, (uint4*)Woh, NW8);

    // fused QKV projections (fp16 in, fp16 out)
    gemm_h<<<dim3(DDIM / GBN, MTOT / GBM, 3), 256, GSMEM>>>(
        xqh, xkh, xvh, Wqh, Wkh, Wvh, nullptr, QHp, KHp, VHp, 1);

    attn_kernel<<<dim3(SS / AQT, BB * HH), ATHR, ASMEM>>>(QHp, KHp, VHp, mask, AHp);

    // output projection (fp16 in, fp32 out)
    gemm_h<<<dim3(DDIM / GBN, MTOT / GBM, 1), 256, GSMEM>>>(
        AHp, AHp, AHp, Woh, Woh, Woh, out, QHp, KHp, VHp, 0);
}

// round 14
// speedup vs baseline: 1.9127x; 1.0373x over previous
#include <cuda_runtime.h>
#include <cuda_fp16.h>
#include <cstdint>

#define BB 4
#define SS 2048
#define DDIM 1024
#define HH 16
#define DKK 64
#define MTOT (BB*SS)   // 8192

// ---------------- scratch (static __device__, allocation-free) ----------------
__device__ __half g_xqh[(size_t)MTOT*DDIM];
__device__ __half g_xkh[(size_t)MTOT*DDIM];
__device__ __half g_xvh[(size_t)MTOT*DDIM];
__device__ __half g_Wh[4][(size_t)DDIM*DDIM];
__device__ __half g_Qh[(size_t)MTOT*DDIM];
__device__ __half g_Kh[(size_t)MTOT*DDIM];
__device__ __half g_Vh[(size_t)MTOT*DDIM];
__device__ __half g_Ah[(size_t)MTOT*DDIM];

// ---------------- helpers ----------------
__device__ __forceinline__ float ex2(float x) {
    float y;
    asm("ex2.approx.ftz.f32 %0, %1;" : "=f"(y) : "f"(x));
    return y;
}
__device__ __forceinline__ uint32_t packh2(float lo, float hi) {
    __half2 h = __floats2half2_rn(lo, hi);
    return *reinterpret_cast<uint32_t*>(&h);
}
__device__ __forceinline__ void cp16(uint32_t saddr, const void* g) {
    asm volatile("cp.async.cg.shared.global [%0], [%1], 16;" :: "r"(saddr), "l"(g));
}
__device__ __forceinline__ void cp4(uint32_t saddr, const void* g) {
    asm volatile("cp.async.ca.shared.global [%0], [%1], 4;" :: "r"(saddr), "l"(g));
}
__device__ __forceinline__ void cp_commit() {
    asm volatile("cp.async.commit_group;");
}
template <int N>
__device__ __forceinline__ void cp_wait() {
    asm volatile("cp.async.wait_group %0;" :: "n"(N));
}
__device__ __forceinline__ void ldsm4(uint32_t& r0, uint32_t& r1, uint32_t& r2, uint32_t& r3,
                                      uint32_t addr) {
    asm volatile("ldmatrix.sync.aligned.m8n8.x4.shared.b16 {%0,%1,%2,%3}, [%4];"
                 : "=r"(r0), "=r"(r1), "=r"(r2), "=r"(r3) : "r"(addr));
}
__device__ __forceinline__ void ldsm4t(uint32_t& r0, uint32_t& r1, uint32_t& r2, uint32_t& r3,
                                       uint32_t addr) {
    asm volatile("ldmatrix.sync.aligned.m8n8.x4.trans.shared.b16 {%0,%1,%2,%3}, [%4];"
                 : "=r"(r0), "=r"(r1), "=r"(r2), "=r"(r3) : "r"(addr));
}
// D(16x8,f32) += A(16x16,f16,row) * B(16x8,f16,col)
__device__ __forceinline__ void mma_f16(float c[4],
                                        uint32_t a0, uint32_t a1, uint32_t a2, uint32_t a3,
                                        uint32_t b0, uint32_t b1) {
    asm volatile(
        "mma.sync.aligned.m16n8k16.row.col.f32.f16.f16.f32 "
        "{%0,%1,%2,%3}, {%4,%5,%6,%7}, {%8,%9}, {%0,%1,%2,%3};"
        : "+f"(c[0]), "+f"(c[1]), "+f"(c[2]), "+f"(c[3])
        : "r"(a0), "r"(a1), "r"(a2), "r"(a3), "r"(b0), "r"(b1));
}

// ---------------- fused fp32 -> fp16 conversion: all 7 tensors, ONE launch ----------------
// z in [0,7): 0-2 activations (NX8 chunks), 3-6 weights (NW8 chunks)
__global__ void f32to16_all(
    const float4* __restrict__ s0, const float4* __restrict__ s1, const float4* __restrict__ s2,
    const float4* __restrict__ s3, const float4* __restrict__ s4, const float4* __restrict__ s5,
    const float4* __restrict__ s6,
    uint4* __restrict__ d0, uint4* __restrict__ d1, uint4* __restrict__ d2,
    uint4* __restrict__ d3, uint4* __restrict__ d4, uint4* __restrict__ d5,
    uint4* __restrict__ d6,
    int nBig, int nSmall) {
    const int z = blockIdx.z;
    const float4* in;
    uint4* out;
    int n8;
    switch (z) {
        case 0: in = s0; out = d0; n8 = nBig; break;
        case 1: in = s1; out = d1; n8 = nBig; break;
        case 2: in = s2; out = d2; n8 = nBig; break;
        case 3: in = s3; out = d3; n8 = nSmall; break;
        case 4: in = s4; out = d4; n8 = nSmall; break;
        case 5: in = s5; out = d5; n8 = nSmall; break;
        default: in = s6; out = d6; n8 = nSmall; break;
    }
    int i = blockIdx.x * blockDim.x + threadIdx.x;
    const int stride = gridDim.x * blockDim.x;
#pragma unroll 2
    for (; i < n8; i += stride) {
        float4 v0 = in[2 * i];
        float4 v1 = in[2 * i + 1];
        uint4 o;
        o.x = packh2(v0.x, v0.y);
        o.y = packh2(v0.z, v0.w);
        o.z = packh2(v1.x, v1.y);
        o.w = packh2(v1.z, v1.w);
        out[i] = o;
    }
}

// ---------------- fp16 GEMM: C[m][n] = sum_k A[m][k] * W[n][k] (R13 proven) ----------------
#define GBM 128
#define GBN 128
#define GBKH 64                               // k per tile (halves)
#define GSTH 72                               // row stride in halves (144B rows)
#define GSTGH (GBM * GSTH)
#define GNS 3
#define GSMEM (2 * GNS * GSTGH * 2)           // 110592 B

__global__ __launch_bounds__(256, 2)
void gemm_h(const __half* __restrict__ A0, const __half* __restrict__ A1, const __half* __restrict__ A2,
            const __half* __restrict__ W0, const __half* __restrict__ W1, const __half* __restrict__ W2,
            float* __restrict__ C,
            __half* __restrict__ H0, __half* __restrict__ H1, __half* __restrict__ H2,
            int outHalf) {
    extern __shared__ __half hsm[];
    __half* Asm = hsm;
    __half* Bsm = hsm + GNS * GSTGH;

    const int z = blockIdx.z;
    const __half* A = (z == 0) ? A0 : (z == 1) ? A1 : A2;
    const __half* W = (z == 0) ? W0 : (z == 1) ? W1 : W2;
    __half* H = (z == 0) ? H0 : (z == 1) ? H1 : H2;

    const int m0 = blockIdx.y * GBM;
    const int n0 = blockIdx.x * GBN;
    const int tid = threadIdx.x;
    const int w = tid >> 5, lane = tid & 31;
    const int g = lane >> 2, tig = lane & 3;
    const int wm = (w >> 2) * 64;
    const int wn = (w & 3) * 32;

    const uint32_t sA = (uint32_t)__cvta_generic_to_shared(Asm);
    const uint32_t sB = (uint32_t)__cvta_generic_to_shared(Bsm);

    const int lane7 = lane & 7;
    const int a_ro = ((lane >> 3) & 1) * 8;
    const int a_kh = ((lane >> 4) & 1) * 8;
    const int b_no = ((lane >> 4) & 1) * 8;
    const int b_kh = ((lane >> 3) & 1) * 8;

    uint32_t aIdx[4];
#pragma unroll
    for (int mt = 0; mt < 4; mt++)
        aIdx[mt] = (uint32_t)(((wm + mt * 16 + a_ro + lane7) * GSTH + a_kh) * 2);
    uint32_t bIdx[2];
#pragma unroll
    for (int nb = 0; nb < 2; nb++)
        bIdx[nb] = (uint32_t)(((wn + nb * 16 + b_no + lane7) * GSTH + b_kh) * 2);

    float acc[4][4][4];
#pragma unroll
    for (int i = 0; i < 4; i++)
#pragma unroll
        for (int j = 0; j < 4; j++)
#pragma unroll
            for (int e = 0; e < 4; e++) acc[i][j][e] = 0.f;

    const int lr = tid >> 3;
    const int lc8 = (tid & 7) << 3;

    auto issue = [&](int st, int k0) {
#pragma unroll
        for (int it = 0; it < 4; it++) {
            int row = lr + it * 32;
            cp16(sA + (uint32_t)((st * GBM + row) * GSTH + lc8) * 2,
                 &A[(size_t)(m0 + row) * DDIM + k0 + lc8]);
            cp16(sB + (uint32_t)((st * GBN + row) * GSTH + lc8) * 2,
                 &W[(size_t)(n0 + row) * DDIM + k0 + lc8]);
        }
    };

    issue(0, 0); cp_commit();
    issue(1, GBKH); cp_commit();

    const int NKT = DDIM / GBKH;      // 16
    for (int kt = 0; kt < NKT; kt++) {
        if (kt < NKT - 1) cp_wait<1>(); else cp_wait<0>();
        __syncthreads();

        const int st = kt % GNS;
        const uint32_t stb = (uint32_t)(st * GSTGH * 2);

#pragma unroll
        for (int ks = 0; ks < 4; ks++) {
            const uint32_t ksB = (uint32_t)(ks * 32);   // 16 halves
            uint32_t b[4][2];
            ldsm4(b[0][0], b[0][1], b[1][0], b[1][1], sB + stb + bIdx[0] + ksB);
            ldsm4(b[2][0], b[2][1], b[3][0], b[3][1], sB + stb + bIdx[1] + ksB);
#pragma unroll
            for (int mt = 0; mt < 4; mt++) {
                uint32_t a0, a1, a2, a3;
                ldsm4(a0, a1, a2, a3, sA + stb + aIdx[mt] + ksB);
#pragma unroll
                for (int nt = 0; nt < 4; nt++)
                    mma_f16(acc[mt][nt], a0, a1, a2, a3, b[nt][0], b[nt][1]);
            }
        }

        if (kt + 2 < NKT) {
            issue((kt + 2) % GNS, (kt + 2) * GBKH);
            cp_commit();
        }
    }

#pragma unroll
    for (int mt = 0; mt < 4; mt++) {
        int r0 = m0 + wm + mt * 16 + g;
#pragma unroll
        for (int nt = 0; nt < 4; nt++) {
            int col = n0 + wn + nt * 8 + 2 * tig;
            float v0 = acc[mt][nt][0], v1 = acc[mt][nt][1];
            float v2 = acc[mt][nt][2], v3 = acc[mt][nt][3];
            if (outHalf) {
                *reinterpret_cast<__half2*>(&H[(size_t)r0 * DDIM + col]) =
                    __floats2half2_rn(v0, v1);
                *reinterpret_cast<__half2*>(&H[(size_t)(r0 + 8) * DDIM + col]) =
                    __floats2half2_rn(v2, v3);
            } else {
                *reinterpret_cast<float2*>(&C[(size_t)r0 * DDIM + col]) = make_float2(v0, v1);
                *reinterpret_cast<float2*>(&C[(size_t)(r0 + 8) * DDIM + col]) = make_float2(v2, v3);
            }
        }
    }
}

// ---------------- flash attention: all-fp16 operands, fp32 accum/softmax (R13 proven) ----------------
#define AQT 256
#define ATHR 256
#define HPH 72    // fp16 row stride (halves)
#define ASMEM ((2*64*HPH + 2*64*HPH + AQT*HPH) * 2 + 2 * 64 * 4)   // 74240 B

__global__ __launch_bounds__(ATHR, 1)
void attn_kernel(const __half* __restrict__ QH, const __half* __restrict__ KH,
                 const __half* __restrict__ VH,
                 const int* __restrict__ mask, __half* __restrict__ O) {
    extern __shared__ uint32_t smem_u[];
    __half* Kh0 = (__half*)smem_u;
    __half* Vh0 = Kh0 + 2 * 64 * HPH;
    __half* Qs  = Vh0 + 2 * 64 * HPH;
    int* msk0 = (int*)(Qs + AQT * HPH);

    const int qi = gridDim.x - 1 - blockIdx.x;     // heavy tiles first
    const int bh = blockIdx.y;
    const int b = bh / HH, h = bh % HH;

    const int tid = threadIdx.x;
    const int w = tid >> 5, lane = tid & 31;
    const int g = lane >> 2, tig = lane & 3;
    const int wrow = w * 32;

    const __half* Qb = QH + ((size_t)b * SS + (size_t)qi * AQT) * DDIM + h * DKK;
    const __half* Kb = KH + (size_t)b * SS * DDIM + h * DKK;
    const __half* Vb = VH + (size_t)b * SS * DDIM + h * DKK;
    __half* Ob = O + ((size_t)b * SS + (size_t)qi * AQT) * DDIM + h * DKK;

    const uint32_t sK = (uint32_t)__cvta_generic_to_shared(Kh0);
    const uint32_t sV = (uint32_t)__cvta_generic_to_shared(Vh0);
    const uint32_t sQ = (uint32_t)__cvta_generic_to_shared(Qs);
    const uint32_t sM = (uint32_t)__cvta_generic_to_shared(msk0);

    const int lane7 = lane & 7;
    const int a_ro = ((lane >> 3) & 1) * 8;
    const int a_kh = ((lane >> 4) & 1) * 8;
    const int b_no = ((lane >> 4) & 1) * 8;
    const int b_kh = ((lane >> 3) & 1) * 8;
    const int v_ro = lane & 15;
    const int v_co = (lane >> 4) * 8;

    const float qscale = 0.125f * 1.4426950408889634f;

    auto issueKV = [&](int st, int kt) {
        const __half* Kt = Kb + (size_t)kt * 64 * DDIM;
        const __half* Vt = Vb + (size_t)kt * 64 * DDIM;
#pragma unroll
        for (int t = 0; t < 2; t++) {
            int i = tid + t * ATHR;
            int r = i >> 3;
            int c8 = (i & 7) << 3;
            uint32_t off = (uint32_t)((st * 64 + r) * HPH + c8) * 2;
            cp16(sK + off, Kt + (size_t)r * DDIM + c8);
            cp16(sV + off, Vt + (size_t)r * DDIM + c8);
        }
        if (tid < 64) cp4(sM + (uint32_t)(st * 64 + tid) * 4, &mask[(size_t)b * SS + kt * 64 + tid]);
    };

    const int ktmax = (AQT / 64) * qi + (AQT / 64) - 1;   // 4*qi + 3
    issueKV(0, 0);
    cp_commit();

    // stage Q (AQT x 64 halves), scaled by qscale
#pragma unroll
    for (int t = 0; t < 8; t++) {
        int i = tid + t * ATHR;
        int r = i >> 3;
        int c8 = (i & 7) << 3;
        uint4 raw = *reinterpret_cast<const uint4*>(Qb + (size_t)r * DDIM + c8);
        const __half2* hp = reinterpret_cast<const __half2*>(&raw);
        uint4 outp;
        uint32_t* op = reinterpret_cast<uint32_t*>(&outp);
#pragma unroll
        for (int e = 0; e < 4; e++) {
            float2 f = __half22float2(hp[e]);
            op[e] = packh2(f.x * qscale, f.y * qscale);
        }
        *reinterpret_cast<uint4*>(&Qs[r * HPH + c8]) = outp;
    }
    __syncthreads();

    uint32_t qf[2][4][4];
#pragma unroll
    for (int mt = 0; mt < 2; mt++) {
        const uint32_t base = sQ + (uint32_t)(((wrow + mt * 16 + a_ro + lane7) * HPH + a_kh) * 2);
#pragma unroll
        for (int ks = 0; ks < 4; ks++)
            ldsm4(qf[mt][ks][0], qf[mt][ks][1], qf[mt][ks][2], qf[mt][ks][3],
                  base + (uint32_t)(ks * 32));
    }

    float mrow[2][2], lrow[2][2];
    float o[2][8][4];
#pragma unroll
    for (int mt = 0; mt < 2; mt++) {
        mrow[mt][0] = mrow[mt][1] = -1e30f;
        lrow[mt][0] = lrow[mt][1] = 0.f;
#pragma unroll
        for (int nt = 0; nt < 8; nt++)
#pragma unroll
            for (int e = 0; e < 4; e++) o[mt][nt][e] = 0.f;
    }

    const int rowmax = qi * AQT + wrow + 31;

    for (int kt = 0; kt <= ktmax; kt++) {
        const int cur = kt & 1;
        __syncthreads();
        if (kt < ktmax) {
            issueKV(cur ^ 1, kt + 1);
            cp_commit();
            cp_wait<1>();
        } else {
            cp_wait<0>();
        }
        __syncthreads();

        const uint32_t sKst = sK + (uint32_t)(cur * 64 * HPH * 2);
        const uint32_t vH0 = sV + (uint32_t)(cur * 64 * HPH * 2)
                           + (uint32_t)(v_ro * HPH + v_co) * 2;
        const int* msk = msk0 + cur * 64;

        if (kt * 64 > rowmax) continue;

        const int mvl0 = msk[lane], mvl1 = msk[32 + lane];
        const bool allvalid = __all_sync(0xffffffffu, (mvl0 != 0) && (mvl1 != 0));

        // S = Q @ K^T : 32x64 per warp, fp16 k16
        float s[2][8][4];
#pragma unroll
        for (int mt = 0; mt < 2; mt++)
#pragma unroll
            for (int nt = 0; nt < 8; nt++)
                s[mt][nt][0] = s[mt][nt][1] = s[mt][nt][2] = s[mt][nt][3] = 0.f;

        const uint32_t kb0 = sKst + (uint32_t)(((b_no + lane7) * HPH + b_kh) * 2);
#pragma unroll
        for (int ks = 0; ks < 4; ks++) {
            const uint32_t ksB = (uint32_t)(ks * 32);
            uint32_t bf[8][2];
#pragma unroll
            for (int j = 0; j < 4; j++)
                ldsm4(bf[2*j][0], bf[2*j][1], bf[2*j+1][0], bf[2*j+1][1],
                      kb0 + (uint32_t)(j * 16 * HPH * 2) + ksB);
#pragma unroll
            for (int mt = 0; mt < 2; mt++)
#pragma unroll
                for (int nt = 0; nt < 8; nt++)
                    mma_f16(s[mt][nt], qf[mt][ks][0], qf[mt][ks][1],
                            qf[mt][ks][2], qf[mt][ks][3], bf[nt][0], bf[nt][1]);
        }

        // masking + online softmax; P packed to fp16 registers
        uint32_t ph[2][8][2];
#pragma unroll
        for (int mt = 0; mt < 2; mt++) {
            const int q0 = qi * AQT + wrow + mt * 16 + g;
            const int q1 = q0 + 8;
            const bool needc = (kt * 64 + 63 > qi * AQT + wrow + mt * 16);

            if (!allvalid) {
#pragma unroll
                for (int nt = 0; nt < 8; nt++) {
                    int cl = nt * 8 + 2 * tig;
                    int cg = kt * 64 + cl;
                    bool mv0 = (msk[cl] != 0);
                    bool mv1 = (msk[cl + 1] != 0);
                    if (!mv0 || (needc && cg > q0))     s[mt][nt][0] = -1e30f;
                    if (!mv1 || (needc && cg + 1 > q0)) s[mt][nt][1] = -1e30f;
                    if (!mv0 || (needc && cg > q1))     s[mt][nt][2] = -1e30f;
                    if (!mv1 || (needc && cg + 1 > q1)) s[mt][nt][3] = -1e30f;
                }
            } else if (needc) {
#pragma unroll
                for (int nt = 0; nt < 8; nt++) {
                    int cg = kt * 64 + nt * 8 + 2 * tig;
                    if (cg > q0)     s[mt][nt][0] = -1e30f;
                    if (cg + 1 > q0) s[mt][nt][1] = -1e30f;
                    if (cg > q1)     s[mt][nt][2] = -1e30f;
                    if (cg + 1 > q1) s[mt][nt][3] = -1e30f;
                }
            }

            float rm0 = -1e30f, rm1 = -1e30f;
#pragma unroll
            for (int nt = 0; nt < 8; nt++) {
                rm0 = fmaxf(rm0, fmaxf(s[mt][nt][0], s[mt][nt][1]));
                rm1 = fmaxf(rm1, fmaxf(s[mt][nt][2], s[mt][nt][3]));
            }
            rm0 = fmaxf(rm0, __shfl_xor_sync(0xffffffffu, rm0, 1));
            rm0 = fmaxf(rm0, __shfl_xor_sync(0xffffffffu, rm0, 2));
            rm1 = fmaxf(rm1, __shfl_xor_sync(0xffffffffu, rm1, 1));
            rm1 = fmaxf(rm1, __shfl_xor_sync(0xffffffffu, rm1, 2));

            float mn0 = fmaxf(mrow[mt][0], rm0);
            float mn1 = fmaxf(mrow[mt][1], rm1);
            float al0 = ex2(mrow[mt][0] - mn0);
            float al1 = ex2(mrow[mt][1] - mn1);
            mrow[mt][0] = mn0; mrow[mt][1] = mn1;

            float rs0 = 0.f, rs1 = 0.f;
#pragma unroll
            for (int nt = 0; nt < 8; nt++) {
                float p0 = ex2(s[mt][nt][0] - mn0);
                float p1 = ex2(s[mt][nt][1] - mn0);
                float p2 = ex2(s[mt][nt][2] - mn1);
                float p3 = ex2(s[mt][nt][3] - mn1);
                rs0 += p0 + p1;
                rs1 += p2 + p3;
                ph[mt][nt][0] = packh2(p0, p1);
                ph[mt][nt][1] = packh2(p2, p3);
            }
            rs0 += __shfl_xor_sync(0xffffffffu, rs0, 1);
            rs0 += __shfl_xor_sync(0xffffffffu, rs0, 2);
            rs1 += __shfl_xor_sync(0xffffffffu, rs1, 1);
            rs1 += __shfl_xor_sync(0xffffffffu, rs1, 2);
            lrow[mt][0] = lrow[mt][0] * al0 + rs0;
            lrow[mt][1] = lrow[mt][1] * al1 + rs1;

#pragma unroll
            for (int nt = 0; nt < 8; nt++) {
                o[mt][nt][0] *= al0; o[mt][nt][1] *= al0;
                o[mt][nt][2] *= al1; o[mt][nt][3] *= al1;
            }
        }

        // O += P @ V, fp16 m16n8k16, P in registers, V via ldmatrix.trans
#pragma unroll
        for (int j = 0; j < 4; j++) {
            const uint32_t jb = (uint32_t)(j * 16 * HPH * 2);
            uint32_t vf[8][2];
#pragma unroll
            for (int dgi = 0; dgi < 4; dgi++)
                ldsm4t(vf[2*dgi][0], vf[2*dgi][1], vf[2*dgi+1][0], vf[2*dgi+1][1],
                       vH0 + jb + (uint32_t)(dgi * 32));
#pragma unroll
            for (int mt = 0; mt < 2; mt++) {
                uint32_t a0 = ph[mt][2*j][0],   a1 = ph[mt][2*j][1];
                uint32_t a2 = ph[mt][2*j+1][0], a3 = ph[mt][2*j+1][1];
#pragma unroll
                for (int nt = 0; nt < 8; nt++)
                    mma_f16(o[mt][nt], a0, a1, a2, a3, vf[nt][0], vf[nt][1]);
            }
        }
    }

    // normalize + store as fp16 (feeds the fp16 Wo GEMM)
#pragma unroll
    for (int mt = 0; mt < 2; mt++) {
        float i0 = 1.f / lrow[mt][0];
        float i1 = 1.f / lrow[mt][1];
        int r0 = wrow + mt * 16 + g;
#pragma unroll
        for (int nt = 0; nt < 8; nt++) {
            int cl = nt * 8 + 2 * tig;
            *reinterpret_cast<__half2*>(&Ob[(size_t)r0 * DDIM + cl]) =
                __floats2half2_rn(o[mt][nt][0] * i0, o[mt][nt][1] * i0);
            *reinterpret_cast<__half2*>(&Ob[(size_t)(r0 + 8) * DDIM + cl]) =
                __floats2half2_rn(o[mt][nt][2] * i1, o[mt][nt][3] * i1);
        }
    }
}

// ---------------- launch ----------------
extern "C" void kernel_launch(void* const* d_in, const int* in_sizes, int n_in,
                              void* d_out, int out_size) {
    const float* xq = (const float*)d_in[0];
    const float* xk = (const float*)d_in[1];
    const float* xv = (const float*)d_in[2];
    const int* mask = (const int*)d_in[3];
    const float* Wq = (const float*)d_in[4];
    const float* Wk = (const float*)d_in[5];
    const float* Wv = (const float*)d_in[6];
    const float* Wo = (const float*)d_in[7];
    float* out = (float*)d_out;

    __half *xqh, *xkh, *xvh, *Wh, *QHp, *KHp, *VHp, *AHp;
    cudaGetSymbolAddress((void**)&xqh, g_xqh);
    cudaGetSymbolAddress((void**)&xkh, g_xkh);
    cudaGetSymbolAddress((void**)&xvh, g_xvh);
    cudaGetSymbolAddress((void**)&Wh, g_Wh);
    cudaGetSymbolAddress((void**)&QHp, g_Qh);
    cudaGetSymbolAddress((void**)&KHp, g_Kh);
    cudaGetSymbolAddress((void**)&VHp, g_Vh);
    cudaGetSymbolAddress((void**)&AHp, g_Ah);

    __half* Wqh = Wh;
    __half* Wkh = Wh + (size_t)DDIM * DDIM;
    __half* Wvh = Wh + 2 * (size_t)DDIM * DDIM;
    __half* Woh = Wh + 3 * (size_t)DDIM * DDIM;

    cudaFuncSetAttribute(gemm_h, cudaFuncAttributeMaxDynamicSharedMemorySize, GSMEM);
    cudaFuncSetAttribute(attn_kernel, cudaFuncAttributeMaxDynamicSharedMemorySize, ASMEM);

    const int NX8 = (MTOT * DDIM) / 8;   // 1048576
    const int NW8 = (DDIM * DDIM) / 8;   // 131072

    // single fused conversion launch: 3 activations + 4 weights
    f32to16_all<<<dim3(512, 1, 7), 256>>>(
        (const float4*)xq, (const float4*)xk, (const float4*)xv,
        (const float4*)Wq, (const float4*)Wk, (const float4*)Wv, (const float4*)Wo,
        (uint4*)xqh, (uint4*)xkh, (uint4*)xvh,
        (uint4*)Wqh, (uint4*)Wkh, (uint4*)Wvh, (uint4*)Woh,
        NX8, NW8);

    // fused QKV projections (fp16 in, fp16 out)
    gemm_h<<<dim3(DDIM / GBN, MTOT / GBM, 3), 256, GSMEM>>>(
        xqh, xkh, xvh, Wqh, Wkh, Wvh, nullptr, QHp, KHp, VHp, 1);

    attn_kernel<<<dim3(SS / AQT, BB * HH), ATHR, ASMEM>>>(QHp, KHp, VHp, mask, AHp);

    // output projection (fp16 in, fp32 out)
    gemm_h<<<dim3(DDIM / GBN, MTOT / GBM, 1), 256, GSMEM>>>(
        AHp, AHp, AHp, Woh, Woh, Woh, out, QHp, KHp, VHp, 0);
}

// round 15
// speedup vs baseline: 1.9713x; 1.0306x over previous
#include <cuda_runtime.h>
#include <cuda_fp16.h>
#include <cstdint>

#define BB 4
#define SS 2048
#define DDIM 1024
#define HH 16
#define DKK 64
#define MTOT (BB*SS)   // 8192

// ---------------- scratch (static __device__, allocation-free) ----------------
__device__ __half g_xqh[(size_t)MTOT*DDIM];
__device__ __half g_xkh[(size_t)MTOT*DDIM];
__device__ __half g_xvh[(size_t)MTOT*DDIM];
__device__ __half g_Wh[4][(size_t)DDIM*DDIM];
__device__ __half g_Qh[(size_t)MTOT*DDIM];
__device__ __half g_Kh[(size_t)MTOT*DDIM];
__device__ __half g_Vh[(size_t)MTOT*DDIM];
__device__ __half g_Ah[(size_t)MTOT*DDIM];

// ---------------- helpers ----------------
__device__ __forceinline__ float ex2(float x) {
    float y;
    asm("ex2.approx.ftz.f32 %0, %1;" : "=f"(y) : "f"(x));
    return y;
}
__device__ __forceinline__ uint32_t packh2(float lo, float hi) {
    __half2 h = __floats2half2_rn(lo, hi);
    return *reinterpret_cast<uint32_t*>(&h);
}
__device__ __forceinline__ void cp16(uint32_t saddr, const void* g) {
    asm volatile("cp.async.cg.shared.global [%0], [%1], 16;" :: "r"(saddr), "l"(g));
}
__device__ __forceinline__ void cp4(uint32_t saddr, const void* g) {
    asm volatile("cp.async.ca.shared.global [%0], [%1], 4;" :: "r"(saddr), "l"(g));
}
__device__ __forceinline__ void cp_commit() {
    asm volatile("cp.async.commit_group;");
}
template <int N>
__device__ __forceinline__ void cp_wait() {
    asm volatile("cp.async.wait_group %0;" :: "n"(N));
}
__device__ __forceinline__ void ldsm4(uint32_t& r0, uint32_t& r1, uint32_t& r2, uint32_t& r3,
                                      uint32_t addr) {
    asm volatile("ldmatrix.sync.aligned.m8n8.x4.shared.b16 {%0,%1,%2,%3}, [%4];"
                 : "=r"(r0), "=r"(r1), "=r"(r2), "=r"(r3) : "r"(addr));
}
__device__ __forceinline__ void ldsm4t(uint32_t& r0, uint32_t& r1, uint32_t& r2, uint32_t& r3,
                                       uint32_t addr) {
    asm volatile("ldmatrix.sync.aligned.m8n8.x4.trans.shared.b16 {%0,%1,%2,%3}, [%4];"
                 : "=r"(r0), "=r"(r1), "=r"(r2), "=r"(r3) : "r"(addr));
}
// D(16x8,f32) += A(16x16,f16,row) * B(16x8,f16,col)
__device__ __forceinline__ void mma_f16(float c[4],
                                        uint32_t a0, uint32_t a1, uint32_t a2, uint32_t a3,
                                        uint32_t b0, uint32_t b1) {
    asm volatile(
        "mma.sync.aligned.m16n8k16.row.col.f32.f16.f16.f32 "
        "{%0,%1,%2,%3}, {%4,%5,%6,%7}, {%8,%9}, {%0,%1,%2,%3};"
        : "+f"(c[0]), "+f"(c[1]), "+f"(c[2]), "+f"(c[3])
        : "r"(a0), "r"(a1), "r"(a2), "r"(a3), "r"(b0), "r"(b1));
}

// ---------------- fused fp32 -> fp16 conversion: all 7 tensors, ONE launch ----------------
__global__ void f32to16_all(
    const float4* __restrict__ s0, const float4* __restrict__ s1, const float4* __restrict__ s2,
    const float4* __restrict__ s3, const float4* __restrict__ s4, const float4* __restrict__ s5,
    const float4* __restrict__ s6,
    uint4* __restrict__ d0, uint4* __restrict__ d1, uint4* __restrict__ d2,
    uint4* __restrict__ d3, uint4* __restrict__ d4, uint4* __restrict__ d5,
    uint4* __restrict__ d6,
    int nBig, int nSmall) {
    const int z = blockIdx.z;
    const float4* in;
    uint4* out;
    int n8;
    switch (z) {
        case 0: in = s0; out = d0; n8 = nBig; break;
        case 1: in = s1; out = d1; n8 = nBig; break;
        case 2: in = s2; out = d2; n8 = nBig; break;
        case 3: in = s3; out = d3; n8 = nSmall; break;
        case 4: in = s4; out = d4; n8 = nSmall; break;
        case 5: in = s5; out = d5; n8 = nSmall; break;
        default: in = s6; out = d6; n8 = nSmall; break;
    }
    int i = blockIdx.x * blockDim.x + threadIdx.x;
    const int stride = gridDim.x * blockDim.x;
#pragma unroll 2
    for (; i < n8; i += stride) {
        float4 v0 = in[2 * i];
        float4 v1 = in[2 * i + 1];
        uint4 o;
        o.x = packh2(v0.x, v0.y);
        o.y = packh2(v0.z, v0.w);
        o.z = packh2(v1.x, v1.y);
        o.w = packh2(v1.z, v1.w);
        out[i] = o;
    }
}

// ---------------- fp16 GEMM: C[m][n] = sum_k A[m][k] * W[n][k] (R13 proven) ----------------
#define GBM 128
#define GBN 128
#define GBKH 64
#define GSTH 72
#define GSTGH (GBM * GSTH)
#define GNS 3
#define GSMEM (2 * GNS * GSTGH * 2)           // 110592 B

__global__ __launch_bounds__(256, 2)
void gemm_h(const __half* __restrict__ A0, const __half* __restrict__ A1, const __half* __restrict__ A2,
            const __half* __restrict__ W0, const __half* __restrict__ W1, const __half* __restrict__ W2,
            float* __restrict__ C,
            __half* __restrict__ H0, __half* __restrict__ H1, __half* __restrict__ H2,
            int outHalf) {
    extern __shared__ __half hsm[];
    __half* Asm = hsm;
    __half* Bsm = hsm + GNS * GSTGH;

    const int z = blockIdx.z;
    const __half* A = (z == 0) ? A0 : (z == 1) ? A1 : A2;
    const __half* W = (z == 0) ? W0 : (z == 1) ? W1 : W2;
    __half* H = (z == 0) ? H0 : (z == 1) ? H1 : H2;

    const int m0 = blockIdx.y * GBM;
    const int n0 = blockIdx.x * GBN;
    const int tid = threadIdx.x;
    const int w = tid >> 5, lane = tid & 31;
    const int g = lane >> 2, tig = lane & 3;
    const int wm = (w >> 2) * 64;
    const int wn = (w & 3) * 32;

    const uint32_t sA = (uint32_t)__cvta_generic_to_shared(Asm);
    const uint32_t sB = (uint32_t)__cvta_generic_to_shared(Bsm);

    const int lane7 = lane & 7;
    const int a_ro = ((lane >> 3) & 1) * 8;
    const int a_kh = ((lane >> 4) & 1) * 8;
    const int b_no = ((lane >> 4) & 1) * 8;
    const int b_kh = ((lane >> 3) & 1) * 8;

    uint32_t aIdx[4];
#pragma unroll
    for (int mt = 0; mt < 4; mt++)
        aIdx[mt] = (uint32_t)(((wm + mt * 16 + a_ro + lane7) * GSTH + a_kh) * 2);
    uint32_t bIdx[2];
#pragma unroll
    for (int nb = 0; nb < 2; nb++)
        bIdx[nb] = (uint32_t)(((wn + nb * 16 + b_no + lane7) * GSTH + b_kh) * 2);

    float acc[4][4][4];
#pragma unroll
    for (int i = 0; i < 4; i++)
#pragma unroll
        for (int j = 0; j < 4; j++)
#pragma unroll
            for (int e = 0; e < 4; e++) acc[i][j][e] = 0.f;

    const int lr = tid >> 3;
    const int lc8 = (tid & 7) << 3;

    auto issue = [&](int st, int k0) {
#pragma unroll
        for (int it = 0; it < 4; it++) {
            int row = lr + it * 32;
            cp16(sA + (uint32_t)((st * GBM + row) * GSTH + lc8) * 2,
                 &A[(size_t)(m0 + row) * DDIM + k0 + lc8]);
            cp16(sB + (uint32_t)((st * GBN + row) * GSTH + lc8) * 2,
                 &W[(size_t)(n0 + row) * DDIM + k0 + lc8]);
        }
    };

    issue(0, 0); cp_commit();
    issue(1, GBKH); cp_commit();

    const int NKT = DDIM / GBKH;      // 16
    for (int kt = 0; kt < NKT; kt++) {
        if (kt < NKT - 1) cp_wait<1>(); else cp_wait<0>();
        __syncthreads();

        const int st = kt % GNS;
        const uint32_t stb = (uint32_t)(st * GSTGH * 2);

#pragma unroll
        for (int ks = 0; ks < 4; ks++) {
            const uint32_t ksB = (uint32_t)(ks * 32);
            uint32_t b[4][2];
            ldsm4(b[0][0], b[0][1], b[1][0], b[1][1], sB + stb + bIdx[0] + ksB);
            ldsm4(b[2][0], b[2][1], b[3][0], b[3][1], sB + stb + bIdx[1] + ksB);
#pragma unroll
            for (int mt = 0; mt < 4; mt++) {
                uint32_t a0, a1, a2, a3;
                ldsm4(a0, a1, a2, a3, sA + stb + aIdx[mt] + ksB);
#pragma unroll
                for (int nt = 0; nt < 4; nt++)
                    mma_f16(acc[mt][nt], a0, a1, a2, a3, b[nt][0], b[nt][1]);
            }
        }

        if (kt + 2 < NKT) {
            issue((kt + 2) % GNS, (kt + 2) * GBKH);
            cp_commit();
        }
    }

#pragma unroll
    for (int mt = 0; mt < 4; mt++) {
        int r0 = m0 + wm + mt * 16 + g;
#pragma unroll
        for (int nt = 0; nt < 4; nt++) {
            int col = n0 + wn + nt * 8 + 2 * tig;
            float v0 = acc[mt][nt][0], v1 = acc[mt][nt][1];
            float v2 = acc[mt][nt][2], v3 = acc[mt][nt][3];
            if (outHalf) {
                *reinterpret_cast<__half2*>(&H[(size_t)r0 * DDIM + col]) =
                    __floats2half2_rn(v0, v1);
                *reinterpret_cast<__half2*>(&H[(size_t)(r0 + 8) * DDIM + col]) =
                    __floats2half2_rn(v2, v3);
            } else {
                *reinterpret_cast<float2*>(&C[(size_t)r0 * DDIM + col]) = make_float2(v0, v1);
                *reinterpret_cast<float2*>(&C[(size_t)(r0 + 8) * DDIM + col]) = make_float2(v2, v3);
            }
        }
    }
}

// ---------------- flash attention: 128-row Q tile, 16 rows/warp, 2 CTAs/SM ----------------
#define AQT 128
#define ATHR 256
#define HPH 72    // fp16 row stride (halves)
#define ASMEM ((2*64*HPH + 2*64*HPH + AQT*HPH) * 2 + 2 * 64 * 4)   // 55808 B

__global__ __launch_bounds__(ATHR, 2)
void attn_kernel(const __half* __restrict__ QH, const __half* __restrict__ KH,
                 const __half* __restrict__ VH,
                 const int* __restrict__ mask, __half* __restrict__ O) {
    extern __shared__ uint32_t smem_u[];
    __half* Kh0 = (__half*)smem_u;
    __half* Vh0 = Kh0 + 2 * 64 * HPH;
    __half* Qs  = Vh0 + 2 * 64 * HPH;              // AQT rows (Q staging, scaled)
    int* msk0 = (int*)(Qs + AQT * HPH);

    const int qi = gridDim.x - 1 - blockIdx.x;     // heavy tiles first
    const int bh = blockIdx.y;
    const int b = bh / HH, h = bh % HH;

    const int tid = threadIdx.x;
    const int w = tid >> 5, lane = tid & 31;
    const int g = lane >> 2, tig = lane & 3;
    const int wrow = w * 16;                       // 16 rows per warp

    const __half* Qb = QH + ((size_t)b * SS + (size_t)qi * AQT) * DDIM + h * DKK;
    const __half* Kb = KH + (size_t)b * SS * DDIM + h * DKK;
    const __half* Vb = VH + (size_t)b * SS * DDIM + h * DKK;
    __half* Ob = O + ((size_t)b * SS + (size_t)qi * AQT) * DDIM + h * DKK;

    const uint32_t sK = (uint32_t)__cvta_generic_to_shared(Kh0);
    const uint32_t sV = (uint32_t)__cvta_generic_to_shared(Vh0);
    const uint32_t sQ = (uint32_t)__cvta_generic_to_shared(Qs);
    const uint32_t sM = (uint32_t)__cvta_generic_to_shared(msk0);

    const int lane7 = lane & 7;
    const int a_ro = ((lane >> 3) & 1) * 8;
    const int a_kh = ((lane >> 4) & 1) * 8;
    const int b_no = ((lane >> 4) & 1) * 8;
    const int b_kh = ((lane >> 3) & 1) * 8;
    const int v_ro = lane & 15;
    const int v_co = (lane >> 4) * 8;

    const float qscale = 0.125f * 1.4426950408889634f;

    auto issueKV = [&](int st, int kt) {
        const __half* Kt = Kb + (size_t)kt * 64 * DDIM;
        const __half* Vt = Vb + (size_t)kt * 64 * DDIM;
#pragma unroll
        for (int t = 0; t < 2; t++) {
            int i = tid + t * ATHR;
            int r = i >> 3;
            int c8 = (i & 7) << 3;
            uint32_t off = (uint32_t)((st * 64 + r) * HPH + c8) * 2;
            cp16(sK + off, Kt + (size_t)r * DDIM + c8);
            cp16(sV + off, Vt + (size_t)r * DDIM + c8);
        }
        if (tid < 64) cp4(sM + (uint32_t)(st * 64 + tid) * 4, &mask[(size_t)b * SS + kt * 64 + tid]);
    };

    const int ktmax = 2 * qi + 1;
    issueKV(0, 0);
    cp_commit();

    // stage Q (AQT x 64 halves), scaled by qscale
#pragma unroll
    for (int t = 0; t < 4; t++) {
        int i = tid + t * ATHR;
        int r = i >> 3;
        int c8 = (i & 7) << 3;
        uint4 raw = *reinterpret_cast<const uint4*>(Qb + (size_t)r * DDIM + c8);
        const __half2* hp = reinterpret_cast<const __half2*>(&raw);
        uint4 outp;
        uint32_t* op = reinterpret_cast<uint32_t*>(&outp);
#pragma unroll
        for (int e = 0; e < 4; e++) {
            float2 f = __half22float2(hp[e]);
            op[e] = packh2(f.x * qscale, f.y * qscale);
        }
        *reinterpret_cast<uint4*>(&Qs[r * HPH + c8]) = outp;
    }
    __syncthreads();

    uint32_t qf[4][4];
    {
        const uint32_t base = sQ + (uint32_t)(((wrow + a_ro + lane7) * HPH + a_kh) * 2);
#pragma unroll
        for (int ks = 0; ks < 4; ks++)
            ldsm4(qf[ks][0], qf[ks][1], qf[ks][2], qf[ks][3],
                  base + (uint32_t)(ks * 32));
    }

    float mrow0 = -1e30f, mrow1 = -1e30f;
    float lrow0 = 0.f, lrow1 = 0.f;
    float o[8][4];
#pragma unroll
    for (int nt = 0; nt < 8; nt++)
#pragma unroll
        for (int e = 0; e < 4; e++) o[nt][e] = 0.f;

    const int rowmax = qi * AQT + wrow + 15;

    for (int kt = 0; kt <= ktmax; kt++) {
        const int cur = kt & 1;
        __syncthreads();
        if (kt < ktmax) {
            issueKV(cur ^ 1, kt + 1);
            cp_commit();
            cp_wait<1>();
        } else {
            cp_wait<0>();
        }
        __syncthreads();

        const uint32_t sKst = sK + (uint32_t)(cur * 64 * HPH * 2);
        const uint32_t vH0 = sV + (uint32_t)(cur * 64 * HPH * 2)
                           + (uint32_t)(v_ro * HPH + v_co) * 2;
        const int* msk = msk0 + cur * 64;

        if (kt * 64 > rowmax) continue;

        const int mvl0 = msk[lane], mvl1 = msk[32 + lane];
        const bool allvalid = __all_sync(0xffffffffu, (mvl0 != 0) && (mvl1 != 0));

        // S = Q @ K^T : 16x64 per warp, fp16 k16
        float s[8][4];
#pragma unroll
        for (int nt = 0; nt < 8; nt++)
            s[nt][0] = s[nt][1] = s[nt][2] = s[nt][3] = 0.f;

        const uint32_t kb0 = sKst + (uint32_t)(((b_no + lane7) * HPH + b_kh) * 2);
#pragma unroll
        for (int ks = 0; ks < 4; ks++) {
            const uint32_t ksB = (uint32_t)(ks * 32);
            uint32_t bf[8][2];
#pragma unroll
            for (int j = 0; j < 4; j++)
                ldsm4(bf[2*j][0], bf[2*j][1], bf[2*j+1][0], bf[2*j+1][1],
                      kb0 + (uint32_t)(j * 16 * HPH * 2) + ksB);
#pragma unroll
            for (int nt = 0; nt < 8; nt++)
                mma_f16(s[nt], qf[ks][0], qf[ks][1], qf[ks][2], qf[ks][3],
                        bf[nt][0], bf[nt][1]);
        }

        // masking + online softmax; P packed to fp16 registers
        const int q0 = qi * AQT + wrow + g;
        const int q1 = q0 + 8;
        const bool needc = (kt * 64 + 63 > qi * AQT + wrow);

        if (!allvalid) {
#pragma unroll
            for (int nt = 0; nt < 8; nt++) {
                int cl = nt * 8 + 2 * tig;
                int cg = kt * 64 + cl;
                bool mv0 = (msk[cl] != 0);
                bool mv1 = (msk[cl + 1] != 0);
                if (!mv0 || (needc && cg > q0))     s[nt][0] = -1e30f;
                if (!mv1 || (needc && cg + 1 > q0)) s[nt][1] = -1e30f;
                if (!mv0 || (needc && cg > q1))     s[nt][2] = -1e30f;
                if (!mv1 || (needc && cg + 1 > q1)) s[nt][3] = -1e30f;
            }
        } else if (needc) {
#pragma unroll
            for (int nt = 0; nt < 8; nt++) {
                int cg = kt * 64 + nt * 8 + 2 * tig;
                if (cg > q0)     s[nt][0] = -1e30f;
                if (cg + 1 > q0) s[nt][1] = -1e30f;
                if (cg > q1)     s[nt][2] = -1e30f;
                if (cg + 1 > q1) s[nt][3] = -1e30f;
            }
        }

        float rm0 = -1e30f, rm1 = -1e30f;
#pragma unroll
        for (int nt = 0; nt < 8; nt++) {
            rm0 = fmaxf(rm0, fmaxf(s[nt][0], s[nt][1]));
            rm1 = fmaxf(rm1, fmaxf(s[nt][2], s[nt][3]));
        }
        rm0 = fmaxf(rm0, __shfl_xor_sync(0xffffffffu, rm0, 1));
        rm0 = fmaxf(rm0, __shfl_xor_sync(0xffffffffu, rm0, 2));
        rm1 = fmaxf(rm1, __shfl_xor_sync(0xffffffffu, rm1, 1));
        rm1 = fmaxf(rm1, __shfl_xor_sync(0xffffffffu, rm1, 2));

        float mn0 = fmaxf(mrow0, rm0);
        float mn1 = fmaxf(mrow1, rm1);
        float al0 = ex2(mrow0 - mn0);
        float al1 = ex2(mrow1 - mn1);
        mrow0 = mn0; mrow1 = mn1;

        uint32_t ph[8][2];
        float rs0 = 0.f, rs1 = 0.f;
#pragma unroll
        for (int nt = 0; nt < 8; nt++) {
            float p0 = ex2(s[nt][0] - mn0);
            float p1 = ex2(s[nt][1] - mn0);
            float p2 = ex2(s[nt][2] - mn1);
            float p3 = ex2(s[nt][3] - mn1);
            rs0 += p0 + p1;
            rs1 += p2 + p3;
            ph[nt][0] = packh2(p0, p1);
            ph[nt][1] = packh2(p2, p3);
        }
        rs0 += __shfl_xor_sync(0xffffffffu, rs0, 1);
        rs0 += __shfl_xor_sync(0xffffffffu, rs0, 2);
        rs1 += __shfl_xor_sync(0xffffffffu, rs1, 1);
        rs1 += __shfl_xor_sync(0xffffffffu, rs1, 2);
        lrow0 = lrow0 * al0 + rs0;
        lrow1 = lrow1 * al1 + rs1;

#pragma unroll
        for (int nt = 0; nt < 8; nt++) {
            o[nt][0] *= al0; o[nt][1] *= al0;
            o[nt][2] *= al1; o[nt][3] *= al1;
        }

        // O += P @ V, fp16 m16n8k16, P in registers, V via ldmatrix.trans
#pragma unroll
        for (int j = 0; j < 4; j++) {
            const uint32_t jb = (uint32_t)(j * 16 * HPH * 2);
            uint32_t vf[8][2];
#pragma unroll
            for (int dgi = 0; dgi < 4; dgi++)
                ldsm4t(vf[2*dgi][0], vf[2*dgi][1], vf[2*dgi+1][0], vf[2*dgi+1][1],
                       vH0 + jb + (uint32_t)(dgi * 32));
            uint32_t a0 = ph[2*j][0],   a1 = ph[2*j][1];
            uint32_t a2 = ph[2*j+1][0], a3 = ph[2*j+1][1];
#pragma unroll
            for (int nt = 0; nt < 8; nt++)
                mma_f16(o[nt], a0, a1, a2, a3, vf[nt][0], vf[nt][1]);
        }
    }

    // normalize + store as fp16 (feeds the fp16 Wo GEMM)
    {
        float i0 = 1.f / lrow0;
        float i1 = 1.f / lrow1;
        int r0 = wrow + g;
#pragma unroll
        for (int nt = 0; nt < 8; nt++) {
            int cl = nt * 8 + 2 * tig;
            *reinterpret_cast<__half2*>(&Ob[(size_t)r0 * DDIM + cl]) =
                __floats2half2_rn(o[nt][0] * i0, o[nt][1] * i0);
            *reinterpret_cast<__half2*>(&Ob[(size_t)(r0 + 8) * DDIM + cl]) =
                __floats2half2_rn(o[nt][2] * i1, o[nt][3] * i1);
        }
    }
}

// ---------------- launch ----------------
extern "C" void kernel_launch(void* const* d_in, const int* in_sizes, int n_in,
                              void* d_out, int out_size) {
    const float* xq = (const float*)d_in[0];
    const float* xk = (const float*)d_in[1];
    const float* xv = (const float*)d_in[2];
    const int* mask = (const int*)d_in[3];
    const float* Wq = (const float*)d_in[4];
    const float* Wk = (const float*)d_in[5];
    const float* Wv = (const float*)d_in[6];
    const float* Wo = (const float*)d_in[7];
    float* out = (float*)d_out;

    __half *xqh, *xkh, *xvh, *Wh, *QHp, *KHp, *VHp, *AHp;
    cudaGetSymbolAddress((void**)&xqh, g_xqh);
    cudaGetSymbolAddress((void**)&xkh, g_xkh);
    cudaGetSymbolAddress((void**)&xvh, g_xvh);
    cudaGetSymbolAddress((void**)&Wh, g_Wh);
    cudaGetSymbolAddress((void**)&QHp, g_Qh);
    cudaGetSymbolAddress((void**)&KHp, g_Kh);
    cudaGetSymbolAddress((void**)&VHp, g_Vh);
    cudaGetSymbolAddress((void**)&AHp, g_Ah);

    __half* Wqh = Wh;
    __half* Wkh = Wh + (size_t)DDIM * DDIM;
    __half* Wvh = Wh + 2 * (size_t)DDIM * DDIM;
    __half* Woh = Wh + 3 * (size_t)DDIM * DDIM;

    cudaFuncSetAttribute(gemm_h, cudaFuncAttributeMaxDynamicSharedMemorySize, GSMEM);
    cudaFuncSetAttribute(attn_kernel, cudaFuncAttributeMaxDynamicSharedMemorySize, ASMEM);

    const int NX8 = (MTOT * DDIM) / 8;   // 1048576
    const int NW8 = (DDIM * DDIM) / 8;   // 131072

    f32to16_all<<<dim3(512, 1, 7), 256>>>(
        (const float4*)xq, (const float4*)xk, (const float4*)xv,
        (const float4*)Wq, (const float4*)Wk, (const float4*)Wv, (const float4*)Wo,
        (uint4*)xqh, (uint4*)xkh, (uint4*)xvh,
        (uint4*)Wqh, (uint4*)Wkh, (uint4*)Wvh, (uint4*)Woh,
        NX8, NW8);

    // fused QKV projections (fp16 in, fp16 out)
    gemm_h<<<dim3(DDIM / GBN, MTOT / GBM, 3), 256, GSMEM>>>(
        xqh, xkh, xvh, Wqh, Wkh, Wvh, nullptr, QHp, KHp, VHp, 1);

    attn_kernel<<<dim3(SS / AQT, BB * HH), ATHR, ASMEM>>>(QHp, KHp, VHp, mask, AHp);

    // output projection (fp16 in, fp32 out)
    gemm_h<<<dim3(DDIM / GBN, MTOT / GBM, 1), 256, GSMEM>>>(
        AHp, AHp, AHp, Woh, Woh, Woh, out, QHp, KHp, VHp, 0);
}